// round 4
// baseline (speedup 1.0000x reference)
#include <cuda_runtime.h>
#include <cuda_bf16.h>
#include <cstdint>
#include <math.h>

#define B_SZ 8
#define S_SZ 2048
#define D_SZ 1024
#define H_SZ 2048
#define M_TOT 16384

// ---------------- scratch (device globals) ------------------------------------
__device__ __nv_bfloat16 g_Xhi[(size_t)M_TOT * D_SZ];
__device__ __nv_bfloat16 g_Xlo[(size_t)M_TOT * D_SZ];
__device__ __nv_bfloat16 g_W1Thi[(size_t)H_SZ * D_SZ];   // [N=2048][K=1024]
__device__ __nv_bfloat16 g_W1Tlo[(size_t)H_SZ * D_SZ];
__device__ __nv_bfloat16 g_W2Thi[(size_t)D_SZ * H_SZ];   // [N=1024][K=2048]
__device__ __nv_bfloat16 g_W2Tlo[(size_t)D_SZ * H_SZ];
__device__ __nv_bfloat16 g_Thi[(size_t)M_TOT * H_SZ];
__device__ __nv_bfloat16 g_Tlo[(size_t)M_TOT * H_SZ];

// ---------------- small PTX helpers (all sm_80-level, compute_103-safe) -------
static __device__ __forceinline__ uint32_t smem_u32(const void* p) {
    uint32_t a;
    asm("{ .reg .u64 t; cvta.to.shared.u64 t, %1; cvt.u32.u64 %0, t; }"
        : "=r"(a) : "l"(p));
    return a;
}
static __device__ __forceinline__ void cpasync16(uint32_t dst, const void* src) {
    asm volatile("cp.async.cg.shared.global [%0], [%1], 16;"
                 :: "r"(dst), "l"(src) : "memory");
}
static __device__ __forceinline__ void cp_commit() {
    asm volatile("cp.async.commit_group;" ::: "memory");
}
template<int N>
static __device__ __forceinline__ void cp_wait() {
    asm volatile("cp.async.wait_group %0;" :: "n"(N) : "memory");
}
static __device__ __forceinline__ void ldsm4(uint32_t* r, uint32_t addr) {
    asm volatile("ldmatrix.sync.aligned.m8n8.x4.shared.b16 {%0,%1,%2,%3}, [%4];"
                 : "=r"(r[0]), "=r"(r[1]), "=r"(r[2]), "=r"(r[3]) : "r"(addr));
}
static __device__ __forceinline__ void mma16816(float* d, const uint32_t* a,
                                                uint32_t b0, uint32_t b1) {
    asm volatile(
        "mma.sync.aligned.m16n8k16.row.col.f32.bf16.bf16.f32 "
        "{%0,%1,%2,%3}, {%4,%5,%6,%7}, {%8,%9}, {%0,%1,%2,%3};"
        : "+f"(d[0]), "+f"(d[1]), "+f"(d[2]), "+f"(d[3])
        : "r"(a[0]), "r"(a[1]), "r"(a[2]), "r"(a[3]), "r"(b0), "r"(b1));
}

// ---------------- prep kernels ------------------------------------------------
static __device__ __forceinline__ void split_one(float x, __nv_bfloat16& h, __nv_bfloat16& l) {
    h = __float2bfloat16(x);
    l = __float2bfloat16(x - __bfloat162float(h));
}

__global__ void split_kernel(const float* __restrict__ X,
                             __nv_bfloat16* __restrict__ Hi,
                             __nv_bfloat16* __restrict__ Lo, int n4) {
    int stride = gridDim.x * blockDim.x;
    for (int i = blockIdx.x * blockDim.x + threadIdx.x; i < n4; i += stride) {
        float4 v = reinterpret_cast<const float4*>(X)[i];
        __nv_bfloat16 h0,h1,h2,h3,l0,l1,l2,l3;
        split_one(v.x,h0,l0); split_one(v.y,h1,l1);
        split_one(v.z,h2,l2); split_one(v.w,h3,l3);
        uint2 ph, pl;
        ph.x = ((uint32_t)__bfloat16_as_ushort(h1) << 16) | __bfloat16_as_ushort(h0);
        ph.y = ((uint32_t)__bfloat16_as_ushort(h3) << 16) | __bfloat16_as_ushort(h2);
        pl.x = ((uint32_t)__bfloat16_as_ushort(l1) << 16) | __bfloat16_as_ushort(l0);
        pl.y = ((uint32_t)__bfloat16_as_ushort(l3) << 16) | __bfloat16_as_ushort(l2);
        reinterpret_cast<uint2*>(Hi)[i] = ph;
        reinterpret_cast<uint2*>(Lo)[i] = pl;
    }
}

// W [R][C] fp32 -> WT_hi/lo [C][R] bf16
__global__ void transpose_split_kernel(const float* __restrict__ W,
                                       __nv_bfloat16* __restrict__ Thi,
                                       __nv_bfloat16* __restrict__ Tlo,
                                       int R, int C) {
    __shared__ float t[32][33];
    int c0 = blockIdx.x * 32, r0 = blockIdx.y * 32;
    int tx = threadIdx.x, ty = threadIdx.y;
    #pragma unroll
    for (int i = ty; i < 32; i += 8)
        t[i][tx] = W[(size_t)(r0 + i) * C + c0 + tx];
    __syncthreads();
    #pragma unroll
    for (int i = ty; i < 32; i += 8) {
        float x = t[tx][i];                 // = W[r0+tx][c0+i]
        __nv_bfloat16 h, l; split_one(x, h, l);
        size_t o = (size_t)(c0 + i) * R + r0 + tx;
        Thi[o] = h; Tlo[o] = l;
    }
}

__global__ void copy_first_token_kernel(const float* __restrict__ X,
                                        float* __restrict__ out) {
    int i = blockIdx.x * blockDim.x + threadIdx.x;
    if (i >= B_SZ * D_SZ) return;
    int b = i >> 10, d = i & 1023;
    size_t off = ((size_t)b * S_SZ) * D_SZ + d;
    out[off] = X[off];
}

// ---------------- HMMA (mma.sync) split-bf16 GEMM -----------------------------
// C[M,N] = act(A·B^T + bias); A [M][K] hi/lo, B [N][K] hi/lo (K-major).
// CTA tile 128x128x32, 4-stage cp.async, 16 warps of 32x32 each.
#define GBM 128
#define GBN 128
#define GBK 32
#define STAGES 4
#define NTHR 512
#define STG_B 32768                 // Ahi 8K | Alo 8K | Bhi 8K | Blo 8K
#define AHI_O 0
#define ALO_O 8192
#define BHI_O 16384
#define BLO_O 24576
#define SMEM_REQ (STAGES * STG_B)   // 128KB

template<int K_TOT, bool FUSE1>
__global__ __launch_bounds__(NTHR, 1)
void hmma_gemm(const __nv_bfloat16* __restrict__ Ahi,
               const __nv_bfloat16* __restrict__ Alo,
               const __nv_bfloat16* __restrict__ Bhi,
               const __nv_bfloat16* __restrict__ Blo,
               const float* __restrict__ bias,
               __nv_bfloat16* __restrict__ OutHi,
               __nv_bfloat16* __restrict__ OutLo,
               float* __restrict__ OutF,
               int Ncols)
{
    extern __shared__ char smem_raw[];
    const uint32_t sbase = smem_u32(smem_raw);

    const int tid = threadIdx.x;
    const int wid = tid >> 5;
    const int l   = tid & 31;
    const int m0  = blockIdx.y * GBM;
    const int n0  = blockIdx.x * GBN;
    const int wm  = wid & 3;        // 4 warp-rows of 32
    const int wn  = wid >> 2;       // 4 warp-cols of 32

    // ---- global->smem load plan: 4 x 16B units per thread -------------------
    // 2048 units: [0,512)=Ahi, [512,1024)=Alo, [1024,1536)=Bhi, [1536,2048)=Blo
    const char* gptr[4];
    uint32_t    soff[4];
    #pragma unroll
    for (int i = 0; i < 4; ++i) {
        int u = i * NTHR + tid;
        int mat = u >> 9;
        int w = u & 511;
        int r = w >> 2, c = w & 3;
        const __nv_bfloat16* src = (mat == 0) ? Ahi : (mat == 1) ? Alo
                                 : (mat == 2) ? Bhi : Blo;
        int grow = ((mat < 2) ? m0 : n0) + r;
        gptr[i] = (const char*)(src + (size_t)grow * K_TOT + c * 8);
        soff[i] = (uint32_t)(mat * 8192 + r * 64) + ((uint32_t)(c ^ ((r >> 1) & 3)) << 4);
    }

    // ---- ldmatrix per-lane address pieces (swizzle: chunk' = c ^ ((row>>1)&3))
    uint32_t aoff[2], axor[2];
    #pragma unroll
    for (int mi = 0; mi < 2; ++mi) {
        int row = wm * 32 + mi * 16 + ((l >> 3) & 1) * 8 + (l & 7);
        aoff[mi] = (uint32_t)row * 64;
        axor[mi] = (uint32_t)((row >> 1) & 3) << 4;
    }
    uint32_t boff[2], bxor[2];
    #pragma unroll
    for (int ni = 0; ni < 2; ++ni) {
        int row = wn * 32 + ni * 16 + ((l >> 4) & 1) * 8 + (l & 7);
        boff[ni] = (uint32_t)row * 64;
        bxor[ni] = (uint32_t)((row >> 1) & 3) << 4;
    }
    const uint32_t a_c = (uint32_t)(l >> 4);        // A k-chunk select per lane
    const uint32_t b_c = (uint32_t)((l >> 3) & 1);  // B k-chunk select per lane

    float acc[2][4][4];
    #pragma unroll
    for (int i = 0; i < 2; ++i)
        #pragma unroll
        for (int j = 0; j < 4; ++j)
            #pragma unroll
            for (int q = 0; q < 4; ++q) acc[i][j][q] = 0.f;

    constexpr int NC = K_TOT / GBK;

    // prologue: fill STAGES-1 stages
    #pragma unroll
    for (int s = 0; s < STAGES - 1; ++s) {
        uint32_t sb = sbase + (uint32_t)s * STG_B;
        #pragma unroll
        for (int i = 0; i < 4; ++i)
            cpasync16(sb + soff[i], gptr[i] + (size_t)s * 64);
        cp_commit();
    }

    #pragma unroll 1
    for (int c = 0; c < NC; ++c) {
        cp_wait<STAGES - 2>();
        __syncthreads();

        // prefetch chunk c+STAGES-1 (stage freed by iteration c-1)
        int pf = c + STAGES - 1;
        if (pf < NC) {
            uint32_t sb = sbase + (uint32_t)(pf % STAGES) * STG_B;
            #pragma unroll
            for (int i = 0; i < 4; ++i)
                cpasync16(sb + soff[i], gptr[i] + (size_t)pf * 64);
        }
        cp_commit();

        const uint32_t sb = sbase + (uint32_t)(c % STAGES) * STG_B;
        #pragma unroll
        for (int step = 0; step < 2; ++step) {
            const uint32_t acx = ((uint32_t)(step * 2) + a_c) << 4;
            const uint32_t bcx = ((uint32_t)(step * 2) + b_c) << 4;

            uint32_t Ah[2][4], Al[2][4], Bh[2][4], Bl[2][4];
            #pragma unroll
            for (int mi = 0; mi < 2; ++mi) {
                ldsm4(Ah[mi], sb + AHI_O + aoff[mi] + (acx ^ axor[mi]));
                ldsm4(Al[mi], sb + ALO_O + aoff[mi] + (acx ^ axor[mi]));
            }
            #pragma unroll
            for (int ni = 0; ni < 2; ++ni) {
                ldsm4(Bh[ni], sb + BHI_O + boff[ni] + (bcx ^ bxor[ni]));
                ldsm4(Bl[ni], sb + BLO_O + boff[ni] + (bcx ^ bxor[ni]));
            }

            #pragma unroll
            for (int mi = 0; mi < 2; ++mi) {
                #pragma unroll
                for (int nj = 0; nj < 4; ++nj) {
                    const int ni = nj >> 1, h = (nj & 1) * 2;
                    mma16816(acc[mi][nj], Ah[mi], Bh[ni][h], Bh[ni][h + 1]);
                    mma16816(acc[mi][nj], Ah[mi], Bl[ni][h], Bl[ni][h + 1]);
                    mma16816(acc[mi][nj], Al[mi], Bh[ni][h], Bh[ni][h + 1]);
                }
            }
        }
    }

    // ---- epilogue -----------------------------------------------------------
    const int r_base = m0 + wm * 32 + (l >> 2);
    const int c_base = n0 + wn * 32 + (l & 3) * 2;
    #pragma unroll
    for (int mi = 0; mi < 2; ++mi) {
        #pragma unroll
        for (int nj = 0; nj < 4; ++nj) {
            const int col = c_base + nj * 8;
            const float bb0 = __ldg(bias + col);
            const float bb1 = __ldg(bias + col + 1);
            #pragma unroll
            for (int hh = 0; hh < 2; ++hh) {
                const int row = r_base + mi * 16 + hh * 8;
                float t0 = acc[mi][nj][hh * 2 + 0] + bb0;
                float t1 = acc[mi][nj][hh * 2 + 1] + bb1;
                if (FUSE1) {
                    t0 = 0.5f * t0 * (1.0f + erff(t0 * 0.70710678118654752f));
                    t1 = 0.5f * t1 * (1.0f + erff(t1 * 0.70710678118654752f));
                    __nv_bfloat16 h0, l0, h1, l1;
                    split_one(t0, h0, l0); split_one(t1, h1, l1);
                    uint32_t ph = ((uint32_t)__bfloat16_as_ushort(h1) << 16) | __bfloat16_as_ushort(h0);
                    uint32_t pl = ((uint32_t)__bfloat16_as_ushort(l1) << 16) | __bfloat16_as_ushort(l0);
                    *reinterpret_cast<uint32_t*>(OutHi + (size_t)row * Ncols + col) = ph;
                    *reinterpret_cast<uint32_t*>(OutLo + (size_t)row * Ncols + col) = pl;
                } else {
                    float2 o; o.x = t0; o.y = t1;
                    *reinterpret_cast<float2*>(OutF + (size_t)row * Ncols + col) = o;
                }
            }
        }
    }
}

// ---------------- launcher ----------------------------------------------------
extern "C" void kernel_launch(void* const* d_in, const int* in_sizes, int n_in,
                              void* d_out, int out_size) {
    (void)in_sizes; (void)n_in; (void)out_size;
    const float* X  = (const float*)d_in[0];
    const float* W1 = (const float*)d_in[1];
    const float* b1 = (const float*)d_in[2];
    const float* W2 = (const float*)d_in[3];
    const float* b2 = (const float*)d_in[4];
    float* out = (float*)d_out;

    __nv_bfloat16 *Xhi, *Xlo, *W1Thi, *W1Tlo, *W2Thi, *W2Tlo, *Thi, *Tlo;
    cudaGetSymbolAddress((void**)&Xhi,   g_Xhi);
    cudaGetSymbolAddress((void**)&Xlo,   g_Xlo);
    cudaGetSymbolAddress((void**)&W1Thi, g_W1Thi);
    cudaGetSymbolAddress((void**)&W1Tlo, g_W1Tlo);
    cudaGetSymbolAddress((void**)&W2Thi, g_W2Thi);
    cudaGetSymbolAddress((void**)&W2Tlo, g_W2Tlo);
    cudaGetSymbolAddress((void**)&Thi,   g_Thi);
    cudaGetSymbolAddress((void**)&Tlo,   g_Tlo);

    cudaFuncSetAttribute(hmma_gemm<D_SZ, true>,
                         cudaFuncAttributeMaxDynamicSharedMemorySize, SMEM_REQ);
    cudaFuncSetAttribute(hmma_gemm<H_SZ, false>,
                         cudaFuncAttributeMaxDynamicSharedMemorySize, SMEM_REQ);

    // 1) split X into hi/lo bf16
    split_kernel<<<4096, 256>>>(X, Xhi, Xlo, M_TOT * D_SZ / 4);
    // 2) transpose+split weights into K-major bf16
    transpose_split_kernel<<<dim3(H_SZ / 32, D_SZ / 32), dim3(32, 8)>>>(W1, W1Thi, W1Tlo, D_SZ, H_SZ);
    transpose_split_kernel<<<dim3(D_SZ / 32, H_SZ / 32), dim3(32, 8)>>>(W2, W2Thi, W2Tlo, H_SZ, D_SZ);
    // 3) GEMM1: T = GELU(X @ W1 + b1), split-bf16 output
    hmma_gemm<D_SZ, true><<<dim3(H_SZ / GBN, M_TOT / GBM), NTHR, SMEM_REQ>>>(
        Xhi, Xlo, W1Thi, W1Tlo, b1, Thi, Tlo, nullptr, H_SZ);
    // 4) GEMM2: out = T @ W2 + b2, fp32 output
    hmma_gemm<H_SZ, false><<<dim3(D_SZ / GBN, M_TOT / GBM), NTHR, SMEM_REQ>>>(
        Thi, Tlo, W2Thi, W2Tlo, b2, nullptr, nullptr, out, D_SZ);
    // 5) out[:,0,:] = X[:,0,:]
    copy_first_token_kernel<<<(B_SZ * D_SZ + 255) / 256, 256>>>(X, out);
}

// round 5
// speedup vs baseline: 1.7506x; 1.7506x over previous
#include <cuda_runtime.h>
#include <cuda_bf16.h>
#include <cstdint>
#include <math.h>

#define B_SZ 8
#define S_SZ 2048
#define D_SZ 1024
#define H_SZ 2048
#define M_TOT 16384

// ---------------- scratch (device globals) ------------------------------------
__device__ __nv_bfloat16 g_Xhi[(size_t)M_TOT * D_SZ];
__device__ __nv_bfloat16 g_Xlo[(size_t)M_TOT * D_SZ];
__device__ __nv_bfloat16 g_W1Thi[(size_t)H_SZ * D_SZ];   // [N=2048][K=1024]
__device__ __nv_bfloat16 g_W1Tlo[(size_t)H_SZ * D_SZ];
__device__ __nv_bfloat16 g_W2Thi[(size_t)D_SZ * H_SZ];   // [N=1024][K=2048]
__device__ __nv_bfloat16 g_W2Tlo[(size_t)D_SZ * H_SZ];
__device__ __nv_bfloat16 g_Thi[(size_t)M_TOT * H_SZ];
__device__ __nv_bfloat16 g_Tlo[(size_t)M_TOT * H_SZ];

// ---------------- small PTX helpers (sm_80-level, compute_103-safe) ------------
static __device__ __forceinline__ uint32_t smem_u32(const void* p) {
    uint32_t a;
    asm("{ .reg .u64 t; cvta.to.shared.u64 t, %1; cvt.u32.u64 %0, t; }"
        : "=r"(a) : "l"(p));
    return a;
}
static __device__ __forceinline__ void cpasync16(uint32_t dst, const void* src) {
    asm volatile("cp.async.cg.shared.global [%0], [%1], 16;"
                 :: "r"(dst), "l"(src) : "memory");
}
static __device__ __forceinline__ void cp_commit() {
    asm volatile("cp.async.commit_group;" ::: "memory");
}
template<int N>
static __device__ __forceinline__ void cp_wait() {
    asm volatile("cp.async.wait_group %0;" :: "n"(N) : "memory");
}
static __device__ __forceinline__ void ldsm4(uint32_t* r, uint32_t addr) {
    asm volatile("ldmatrix.sync.aligned.m8n8.x4.shared.b16 {%0,%1,%2,%3}, [%4];"
                 : "=r"(r[0]), "=r"(r[1]), "=r"(r[2]), "=r"(r[3]) : "r"(addr));
}
static __device__ __forceinline__ void mma16816(float* d, const uint32_t* a,
                                                uint32_t b0, uint32_t b1) {
    asm volatile(
        "mma.sync.aligned.m16n8k16.row.col.f32.bf16.bf16.f32 "
        "{%0,%1,%2,%3}, {%4,%5,%6,%7}, {%8,%9}, {%0,%1,%2,%3};"
        : "+f"(d[0]), "+f"(d[1]), "+f"(d[2]), "+f"(d[3])
        : "r"(a[0]), "r"(a[1]), "r"(a[2]), "r"(a[3]), "r"(b0), "r"(b1));
}

// ---------------- prep kernels ------------------------------------------------
static __device__ __forceinline__ void split_one(float x, __nv_bfloat16& h, __nv_bfloat16& l) {
    h = __float2bfloat16(x);
    l = __float2bfloat16(x - __bfloat162float(h));
}

__global__ void split_kernel(const float* __restrict__ X,
                             __nv_bfloat16* __restrict__ Hi,
                             __nv_bfloat16* __restrict__ Lo, int n4) {
    int stride = gridDim.x * blockDim.x;
    for (int i = blockIdx.x * blockDim.x + threadIdx.x; i < n4; i += stride) {
        float4 v = reinterpret_cast<const float4*>(X)[i];
        __nv_bfloat16 h0,h1,h2,h3,l0,l1,l2,l3;
        split_one(v.x,h0,l0); split_one(v.y,h1,l1);
        split_one(v.z,h2,l2); split_one(v.w,h3,l3);
        uint2 ph, pl;
        ph.x = ((uint32_t)__bfloat16_as_ushort(h1) << 16) | __bfloat16_as_ushort(h0);
        ph.y = ((uint32_t)__bfloat16_as_ushort(h3) << 16) | __bfloat16_as_ushort(h2);
        pl.x = ((uint32_t)__bfloat16_as_ushort(l1) << 16) | __bfloat16_as_ushort(l0);
        pl.y = ((uint32_t)__bfloat16_as_ushort(l3) << 16) | __bfloat16_as_ushort(l2);
        reinterpret_cast<uint2*>(Hi)[i] = ph;
        reinterpret_cast<uint2*>(Lo)[i] = pl;
    }
}

// W [R][C] fp32 -> WT_hi/lo [C][R] bf16
__global__ void transpose_split_kernel(const float* __restrict__ W,
                                       __nv_bfloat16* __restrict__ Thi,
                                       __nv_bfloat16* __restrict__ Tlo,
                                       int R, int C) {
    __shared__ float t[32][33];
    int c0 = blockIdx.x * 32, r0 = blockIdx.y * 32;
    int tx = threadIdx.x, ty = threadIdx.y;
    #pragma unroll
    for (int i = ty; i < 32; i += 8)
        t[i][tx] = W[(size_t)(r0 + i) * C + c0 + tx];
    __syncthreads();
    #pragma unroll
    for (int i = ty; i < 32; i += 8) {
        float x = t[tx][i];                 // = W[r0+tx][c0+i]
        __nv_bfloat16 h, l; split_one(x, h, l);
        size_t o = (size_t)(c0 + i) * R + r0 + tx;
        Thi[o] = h; Tlo[o] = l;
    }
}

__global__ void copy_first_token_kernel(const float* __restrict__ X,
                                        float* __restrict__ out) {
    int i = blockIdx.x * blockDim.x + threadIdx.x;
    if (i >= B_SZ * D_SZ) return;
    int b = i >> 10, d = i & 1023;
    size_t off = ((size_t)b * S_SZ) * D_SZ + d;
    out[off] = X[off];
}

// ---------------- HMMA (mma.sync) split-bf16 GEMM -----------------------------
// C[M,N] = act(A·B^T + bias); A [M][K] hi/lo, B [N][K] hi/lo (K-major).
// CTA tile 128x128x64, 2-stage cp.async, 8 warps of 64x32.
// Fragment double-buffering hides LDSM latency inside the 4 k16-steps/chunk.
#define GBM 128
#define GBN 128
#define GBK 64
#define NTHR 256
#define STG_B 65536                 // Ahi 16K | Alo 16K | Bhi 16K | Blo 16K
#define AHI_O 0
#define ALO_O 16384
#define BHI_O 32768
#define BLO_O 49152
#define SMEM_REQ (2 * STG_B)        // 128KB

#define LOAD_FRAGS(BUF, SB, STEP) do {                                         \
    const uint32_t acx = (uint32_t)((STEP) * 2) + a_c;                         \
    const uint32_t bcx = (uint32_t)((STEP) * 2) + b_c;                         \
    _Pragma("unroll")                                                          \
    for (int mi_ = 0; mi_ < 4; ++mi_) {                                        \
        uint32_t ad = (SB) + aAddr[mi_] + ((acx ^ aSw[mi_]) << 4);             \
        ldsm4(Ah[BUF][mi_], ad);                                               \
        ldsm4(Al[BUF][mi_], ad + (ALO_O - AHI_O));                             \
    }                                                                          \
    _Pragma("unroll")                                                          \
    for (int ni_ = 0; ni_ < 2; ++ni_) {                                        \
        uint32_t bd = (SB) + bAddr[ni_] + ((bcx ^ bSw[ni_]) << 4);             \
        ldsm4(Bh[BUF][ni_], bd);                                               \
        ldsm4(Bl[BUF][ni_], bd + (BLO_O - BHI_O));                             \
    }                                                                          \
} while (0)

#define MMA_STEP(BUF) do {                                                     \
    _Pragma("unroll")                                                          \
    for (int mi_ = 0; mi_ < 4; ++mi_) {                                        \
        _Pragma("unroll")                                                      \
        for (int nj_ = 0; nj_ < 4; ++nj_) {                                    \
            const int ni_ = nj_ >> 1, h_ = (nj_ & 1) * 2;                      \
            mma16816(acc[mi_][nj_], Ah[BUF][mi_], Bh[BUF][ni_][h_], Bh[BUF][ni_][h_ + 1]); \
            mma16816(acc[mi_][nj_], Ah[BUF][mi_], Bl[BUF][ni_][h_], Bl[BUF][ni_][h_ + 1]); \
            mma16816(acc[mi_][nj_], Al[BUF][mi_], Bh[BUF][ni_][h_], Bh[BUF][ni_][h_ + 1]); \
        }                                                                      \
    }                                                                          \
} while (0)

template<int K_TOT, bool FUSE1>
__global__ __launch_bounds__(NTHR, 1)
void hmma_gemm(const __nv_bfloat16* __restrict__ Ahi,
               const __nv_bfloat16* __restrict__ Alo,
               const __nv_bfloat16* __restrict__ Bhi,
               const __nv_bfloat16* __restrict__ Blo,
               const float* __restrict__ bias,
               __nv_bfloat16* __restrict__ OutHi,
               __nv_bfloat16* __restrict__ OutLo,
               float* __restrict__ OutF,
               int Ncols)
{
    extern __shared__ char smem_raw[];
    const uint32_t sbase = smem_u32(smem_raw);

    const int tid = threadIdx.x;
    const int wid = tid >> 5;
    const int l   = tid & 31;
    const int m0  = blockIdx.y * GBM;
    const int n0  = blockIdx.x * GBN;
    const int wm  = wid & 1;        // 2 warp-rows of 64
    const int wn  = wid >> 1;       // 4 warp-cols of 32

    // ---- global->smem load plan: 16 x 16B units per thread ------------------
    // unit i (0..15): mat = i>>2, row = (i&3)*32 + (tid>>3), chunk16B = tid&7
    const char* pb[4];
    {
        const int r0 = tid >> 3, cc = tid & 7;
        pb[0] = (const char*)(Ahi + (size_t)(m0 + r0) * K_TOT) + cc * 16;
        pb[1] = (const char*)(Alo + (size_t)(m0 + r0) * K_TOT) + cc * 16;
        pb[2] = (const char*)(Bhi + (size_t)(n0 + r0) * K_TOT) + cc * 16;
        pb[3] = (const char*)(Blo + (size_t)(n0 + r0) * K_TOT) + cc * 16;
    }
    // soff_i = i*4096 + s0 ; swizzle: chunk' = chunk ^ (row & 7)
    const uint32_t s0 = (uint32_t)((tid >> 3) * 128)
                      + ((uint32_t)((tid & 7) ^ ((tid >> 3) & 7)) << 4);

    // ---- ldmatrix address pieces -------------------------------------------
    uint32_t aAddr[4], aSw[4], bAddr[2], bSw[2];
    #pragma unroll
    for (int mi = 0; mi < 4; ++mi) {
        int row = wm * 64 + mi * 16 + ((l >> 3) & 1) * 8 + (l & 7);
        aAddr[mi] = AHI_O + (uint32_t)row * 128;
        aSw[mi]   = (uint32_t)(row & 7);
    }
    #pragma unroll
    for (int ni = 0; ni < 2; ++ni) {
        int row = wn * 32 + ni * 16 + ((l >> 4) & 1) * 8 + (l & 7);
        bAddr[ni] = BHI_O + (uint32_t)row * 128;
        bSw[ni]   = (uint32_t)(row & 7);
    }
    const uint32_t a_c = (uint32_t)(l >> 4);
    const uint32_t b_c = (uint32_t)((l >> 3) & 1);

    float acc[4][4][4];
    #pragma unroll
    for (int i = 0; i < 4; ++i)
        #pragma unroll
        for (int j = 0; j < 4; ++j)
            #pragma unroll
            for (int q = 0; q < 4; ++q) acc[i][j][q] = 0.f;

    uint32_t Ah[2][4][4], Al[2][4][4], Bh[2][2][4], Bl[2][2][4];

    constexpr int NC = K_TOT / GBK;

    // prologue: fill both stages
    #pragma unroll
    for (int s = 0; s < 2; ++s) {
        const uint32_t sb = sbase + (uint32_t)s * STG_B;
        #pragma unroll
        for (int i = 0; i < 16; ++i)
            cpasync16(sb + (uint32_t)i * 4096 + s0,
                      pb[i >> 2] + (size_t)((i & 3) * 32) * K_TOT * 2 + (size_t)s * 128);
        cp_commit();
    }
    cp_wait<1>();
    __syncthreads();
    LOAD_FRAGS(0, sbase, 0);

    #pragma unroll 1
    for (int c = 0; c < NC; ++c) {
        const uint32_t sb = sbase + (uint32_t)(c & 1) * STG_B;
        #pragma unroll
        for (int step = 0; step < 4; ++step) {
            if (step < 3) LOAD_FRAGS((step + 1) & 1, sb, step + 1);
            MMA_STEP(step & 1);
        }
        __syncthreads();                 // all warps done reading stage c&1
        if (c + 2 < NC) {
            #pragma unroll
            for (int i = 0; i < 16; ++i)
                cpasync16(sb + (uint32_t)i * 4096 + s0,
                          pb[i >> 2] + (size_t)((i & 3) * 32) * K_TOT * 2
                                     + (size_t)(c + 2) * 128);
        }
        cp_commit();
        cp_wait<1>();                    // own group for chunk c+1 complete
        __syncthreads();                 // everyone's c+1 data visible
        if (c + 1 < NC)
            LOAD_FRAGS(0, sbase + (uint32_t)((c + 1) & 1) * STG_B, 0);
    }

    // ---- epilogue -----------------------------------------------------------
    const int r_base = m0 + wm * 64 + (l >> 2);
    const int c_base = n0 + wn * 32 + (l & 3) * 2;
    #pragma unroll
    for (int mi = 0; mi < 4; ++mi) {
        #pragma unroll
        for (int nj = 0; nj < 4; ++nj) {
            const int col = c_base + nj * 8;
            const float bb0 = __ldg(bias + col);
            const float bb1 = __ldg(bias + col + 1);
            #pragma unroll
            for (int hh = 0; hh < 2; ++hh) {
                const int row = r_base + mi * 16 + hh * 8;
                float t0 = acc[mi][nj][hh * 2 + 0] + bb0;
                float t1 = acc[mi][nj][hh * 2 + 1] + bb1;
                if (FUSE1) {
                    t0 = 0.5f * t0 * (1.0f + erff(t0 * 0.70710678118654752f));
                    t1 = 0.5f * t1 * (1.0f + erff(t1 * 0.70710678118654752f));
                    __nv_bfloat16 h0, l0, h1, l1;
                    split_one(t0, h0, l0); split_one(t1, h1, l1);
                    uint32_t ph = ((uint32_t)__bfloat16_as_ushort(h1) << 16) | __bfloat16_as_ushort(h0);
                    uint32_t pl = ((uint32_t)__bfloat16_as_ushort(l1) << 16) | __bfloat16_as_ushort(l0);
                    *reinterpret_cast<uint32_t*>(OutHi + (size_t)row * Ncols + col) = ph;
                    *reinterpret_cast<uint32_t*>(OutLo + (size_t)row * Ncols + col) = pl;
                } else {
                    float2 o; o.x = t0; o.y = t1;
                    *reinterpret_cast<float2*>(OutF + (size_t)row * Ncols + col) = o;
                }
            }
        }
    }
}

// ---------------- launcher ----------------------------------------------------
extern "C" void kernel_launch(void* const* d_in, const int* in_sizes, int n_in,
                              void* d_out, int out_size) {
    (void)in_sizes; (void)n_in; (void)out_size;
    const float* X  = (const float*)d_in[0];
    const float* W1 = (const float*)d_in[1];
    const float* b1 = (const float*)d_in[2];
    const float* W2 = (const float*)d_in[3];
    const float* b2 = (const float*)d_in[4];
    float* out = (float*)d_out;

    __nv_bfloat16 *Xhi, *Xlo, *W1Thi, *W1Tlo, *W2Thi, *W2Tlo, *Thi, *Tlo;
    cudaGetSymbolAddress((void**)&Xhi,   g_Xhi);
    cudaGetSymbolAddress((void**)&Xlo,   g_Xlo);
    cudaGetSymbolAddress((void**)&W1Thi, g_W1Thi);
    cudaGetSymbolAddress((void**)&W1Tlo, g_W1Tlo);
    cudaGetSymbolAddress((void**)&W2Thi, g_W2Thi);
    cudaGetSymbolAddress((void**)&W2Tlo, g_W2Tlo);
    cudaGetSymbolAddress((void**)&Thi,   g_Thi);
    cudaGetSymbolAddress((void**)&Tlo,   g_Tlo);

    cudaFuncSetAttribute(hmma_gemm<D_SZ, true>,
                         cudaFuncAttributeMaxDynamicSharedMemorySize, SMEM_REQ);
    cudaFuncSetAttribute(hmma_gemm<H_SZ, false>,
                         cudaFuncAttributeMaxDynamicSharedMemorySize, SMEM_REQ);

    // 1) split X into hi/lo bf16
    split_kernel<<<4096, 256>>>(X, Xhi, Xlo, M_TOT * D_SZ / 4);
    // 2) transpose+split weights into K-major bf16
    transpose_split_kernel<<<dim3(H_SZ / 32, D_SZ / 32), dim3(32, 8)>>>(W1, W1Thi, W1Tlo, D_SZ, H_SZ);
    transpose_split_kernel<<<dim3(D_SZ / 32, H_SZ / 32), dim3(32, 8)>>>(W2, W2Thi, W2Tlo, H_SZ, D_SZ);
    // 3) GEMM1: T = GELU(X @ W1 + b1), split-bf16 output
    hmma_gemm<D_SZ, true><<<dim3(H_SZ / GBN, M_TOT / GBM), NTHR, SMEM_REQ>>>(
        Xhi, Xlo, W1Thi, W1Tlo, b1, Thi, Tlo, nullptr, H_SZ);
    // 4) GEMM2: out = T @ W2 + b2, fp32 output
    hmma_gemm<H_SZ, false><<<dim3(D_SZ / GBN, M_TOT / GBM), NTHR, SMEM_REQ>>>(
        Thi, Tlo, W2Thi, W2Tlo, b2, nullptr, nullptr, out, D_SZ);
    // 5) out[:,0,:] = X[:,0,:]
    copy_first_token_kernel<<<(B_SZ * D_SZ + 255) / 256, 256>>>(X, out);
}

// round 6
// speedup vs baseline: 1.7843x; 1.0192x over previous
#include <cuda_runtime.h>
#include <cuda_bf16.h>
#include <cstdint>
#include <math.h>

#define B_SZ 8
#define S_SZ 2048
#define D_SZ 1024
#define H_SZ 2048
#define M_TOT 16384

// ---------------- scratch (device globals) ------------------------------------
__device__ __nv_bfloat16 g_Xhi[(size_t)M_TOT * D_SZ];
__device__ __nv_bfloat16 g_Xlo[(size_t)M_TOT * D_SZ];
__device__ __nv_bfloat16 g_W1Thi[(size_t)H_SZ * D_SZ];   // [N=2048][K=1024]
__device__ __nv_bfloat16 g_W1Tlo[(size_t)H_SZ * D_SZ];
__device__ __nv_bfloat16 g_W2Thi[(size_t)D_SZ * H_SZ];   // [N=1024][K=2048]
__device__ __nv_bfloat16 g_W2Tlo[(size_t)D_SZ * H_SZ];
__device__ __nv_bfloat16 g_Thi[(size_t)M_TOT * H_SZ];
__device__ __nv_bfloat16 g_Tlo[(size_t)M_TOT * H_SZ];

// ---------------- small PTX helpers (sm_80-level, compute_103-safe) ------------
static __device__ __forceinline__ uint32_t smem_u32(const void* p) {
    uint32_t a;
    asm("{ .reg .u64 t; cvta.to.shared.u64 t, %1; cvt.u32.u64 %0, t; }"
        : "=r"(a) : "l"(p));
    return a;
}
static __device__ __forceinline__ void cpasync16(uint32_t dst, const void* src) {
    asm volatile("cp.async.cg.shared.global [%0], [%1], 16;"
                 :: "r"(dst), "l"(src) : "memory");
}
static __device__ __forceinline__ void cp_commit() {
    asm volatile("cp.async.commit_group;" ::: "memory");
}
template<int N>
static __device__ __forceinline__ void cp_wait() {
    asm volatile("cp.async.wait_group %0;" :: "n"(N) : "memory");
}
static __device__ __forceinline__ void ldsm4(uint32_t* r, uint32_t addr) {
    asm volatile("ldmatrix.sync.aligned.m8n8.x4.shared.b16 {%0,%1,%2,%3}, [%4];"
                 : "=r"(r[0]), "=r"(r[1]), "=r"(r[2]), "=r"(r[3]) : "r"(addr));
}
static __device__ __forceinline__ void mma16816(float* d, const uint32_t* a,
                                                uint32_t b0, uint32_t b1) {
    asm volatile(
        "mma.sync.aligned.m16n8k16.row.col.f32.bf16.bf16.f32 "
        "{%0,%1,%2,%3}, {%4,%5,%6,%7}, {%8,%9}, {%0,%1,%2,%3};"
        : "+f"(d[0]), "+f"(d[1]), "+f"(d[2]), "+f"(d[3])
        : "r"(a[0]), "r"(a[1]), "r"(a[2]), "r"(a[3]), "r"(b0), "r"(b1));
}

// ---------------- prep kernels ------------------------------------------------
static __device__ __forceinline__ void split_one(float x, __nv_bfloat16& h, __nv_bfloat16& l) {
    h = __float2bfloat16(x);
    l = __float2bfloat16(x - __bfloat162float(h));
}

__global__ void split_kernel(const float* __restrict__ X,
                             __nv_bfloat16* __restrict__ Hi,
                             __nv_bfloat16* __restrict__ Lo, int n4) {
    int stride = gridDim.x * blockDim.x;
    for (int i = blockIdx.x * blockDim.x + threadIdx.x; i < n4; i += stride) {
        float4 v = reinterpret_cast<const float4*>(X)[i];
        __nv_bfloat16 h0,h1,h2,h3,l0,l1,l2,l3;
        split_one(v.x,h0,l0); split_one(v.y,h1,l1);
        split_one(v.z,h2,l2); split_one(v.w,h3,l3);
        uint2 ph, pl;
        ph.x = ((uint32_t)__bfloat16_as_ushort(h1) << 16) | __bfloat16_as_ushort(h0);
        ph.y = ((uint32_t)__bfloat16_as_ushort(h3) << 16) | __bfloat16_as_ushort(h2);
        pl.x = ((uint32_t)__bfloat16_as_ushort(l1) << 16) | __bfloat16_as_ushort(l0);
        pl.y = ((uint32_t)__bfloat16_as_ushort(l3) << 16) | __bfloat16_as_ushort(l2);
        reinterpret_cast<uint2*>(Hi)[i] = ph;
        reinterpret_cast<uint2*>(Lo)[i] = pl;
    }
}

// W [R][C] fp32 -> WT_hi/lo [C][R] bf16
__global__ void transpose_split_kernel(const float* __restrict__ W,
                                       __nv_bfloat16* __restrict__ Thi,
                                       __nv_bfloat16* __restrict__ Tlo,
                                       int R, int C) {
    __shared__ float t[32][33];
    int c0 = blockIdx.x * 32, r0 = blockIdx.y * 32;
    int tx = threadIdx.x, ty = threadIdx.y;
    #pragma unroll
    for (int i = ty; i < 32; i += 8)
        t[i][tx] = W[(size_t)(r0 + i) * C + c0 + tx];
    __syncthreads();
    #pragma unroll
    for (int i = ty; i < 32; i += 8) {
        float x = t[tx][i];                 // = W[r0+tx][c0+i]
        __nv_bfloat16 h, l; split_one(x, h, l);
        size_t o = (size_t)(c0 + i) * R + r0 + tx;
        Thi[o] = h; Tlo[o] = l;
    }
}

__global__ void copy_first_token_kernel(const float* __restrict__ X,
                                        float* __restrict__ out) {
    int i = blockIdx.x * blockDim.x + threadIdx.x;
    if (i >= B_SZ * D_SZ) return;
    int b = i >> 10, d = i & 1023;
    size_t off = ((size_t)b * S_SZ) * D_SZ + d;
    out[off] = X[off];
}

// ---------------- HMMA (mma.sync) split-bf16 GEMM -----------------------------
// C[M,N] = act(A·B^T + bias); A [M][K] hi/lo, B [N][K] hi/lo (K-major).
// CTA tile 128x128x64, 3-stage cp.async (192KB), 8 warps of 64x32.
// Fragment double-buffering hides LDSM latency inside the 4 k16-steps/chunk.
#define GBM 128
#define GBN 128
#define GBK 64
#define NTHR 256
#define STAGES 3
#define STG_B 65536                 // Ahi 16K | Alo 16K | Bhi 16K | Blo 16K
#define AHI_O 0
#define ALO_O 16384
#define BHI_O 32768
#define BLO_O 49152
#define SMEM_REQ (STAGES * STG_B)   // 192KB

#define LOAD_FRAGS(BUF, SB, STEP) do {                                         \
    const uint32_t acx = (uint32_t)((STEP) * 2) + a_c;                         \
    const uint32_t bcx = (uint32_t)((STEP) * 2) + b_c;                         \
    _Pragma("unroll")                                                          \
    for (int mi_ = 0; mi_ < 4; ++mi_) {                                        \
        uint32_t ad = (SB) + aAddr[mi_] + ((acx ^ aSw[mi_]) << 4);             \
        ldsm4(Ah[BUF][mi_], ad);                                               \
        ldsm4(Al[BUF][mi_], ad + (ALO_O - AHI_O));                             \
    }                                                                          \
    _Pragma("unroll")                                                          \
    for (int ni_ = 0; ni_ < 2; ++ni_) {                                        \
        uint32_t bd = (SB) + bAddr[ni_] + ((bcx ^ bSw[ni_]) << 4);             \
        ldsm4(Bh[BUF][ni_], bd);                                               \
        ldsm4(Bl[BUF][ni_], bd + (BLO_O - BHI_O));                             \
    }                                                                          \
} while (0)

#define MMA_STEP(BUF) do {                                                     \
    _Pragma("unroll")                                                          \
    for (int mi_ = 0; mi_ < 4; ++mi_) {                                        \
        _Pragma("unroll")                                                      \
        for (int nj_ = 0; nj_ < 4; ++nj_) {                                    \
            const int ni_ = nj_ >> 1, h_ = (nj_ & 1) * 2;                      \
            mma16816(acc[mi_][nj_], Ah[BUF][mi_], Bh[BUF][ni_][h_], Bh[BUF][ni_][h_ + 1]); \
            mma16816(acc[mi_][nj_], Ah[BUF][mi_], Bl[BUF][ni_][h_], Bl[BUF][ni_][h_ + 1]); \
            mma16816(acc[mi_][nj_], Al[BUF][mi_], Bh[BUF][ni_][h_], Bh[BUF][ni_][h_ + 1]); \
        }                                                                      \
    }                                                                          \
} while (0)

template<int K_TOT, bool FUSE1>
__global__ __launch_bounds__(NTHR, 1)
void hmma_gemm(const __nv_bfloat16* __restrict__ Ahi,
               const __nv_bfloat16* __restrict__ Alo,
               const __nv_bfloat16* __restrict__ Bhi,
               const __nv_bfloat16* __restrict__ Blo,
               const float* __restrict__ bias,
               __nv_bfloat16* __restrict__ OutHi,
               __nv_bfloat16* __restrict__ OutLo,
               float* __restrict__ OutF,
               int Ncols)
{
    extern __shared__ char smem_raw[];
    const uint32_t sbase = smem_u32(smem_raw);

    const int tid = threadIdx.x;
    const int wid = tid >> 5;
    const int l   = tid & 31;
    const int m0  = blockIdx.y * GBM;
    const int n0  = blockIdx.x * GBN;
    const int wm  = wid & 1;        // 2 warp-rows of 64
    const int wn  = wid >> 1;       // 4 warp-cols of 32

    // ---- global->smem load plan: 16 x 16B units per thread ------------------
    // unit i (0..15): mat = i>>2, row = (i&3)*32 + (tid>>3), chunk16B = tid&7
    const char* pb[4];
    {
        const int r0 = tid >> 3, cc = tid & 7;
        pb[0] = (const char*)(Ahi + (size_t)(m0 + r0) * K_TOT) + cc * 16;
        pb[1] = (const char*)(Alo + (size_t)(m0 + r0) * K_TOT) + cc * 16;
        pb[2] = (const char*)(Bhi + (size_t)(n0 + r0) * K_TOT) + cc * 16;
        pb[3] = (const char*)(Blo + (size_t)(n0 + r0) * K_TOT) + cc * 16;
    }
    // soff_i = i*4096 + s0 ; swizzle: chunk' = chunk ^ (row & 7)
    const uint32_t s0 = (uint32_t)((tid >> 3) * 128)
                      + ((uint32_t)((tid & 7) ^ ((tid >> 3) & 7)) << 4);

    // ---- ldmatrix address pieces -------------------------------------------
    uint32_t aAddr[4], aSw[4], bAddr[2], bSw[2];
    #pragma unroll
    for (int mi = 0; mi < 4; ++mi) {
        int row = wm * 64 + mi * 16 + ((l >> 3) & 1) * 8 + (l & 7);
        aAddr[mi] = AHI_O + (uint32_t)row * 128;
        aSw[mi]   = (uint32_t)(row & 7);
    }
    #pragma unroll
    for (int ni = 0; ni < 2; ++ni) {
        int row = wn * 32 + ni * 16 + ((l >> 4) & 1) * 8 + (l & 7);
        bAddr[ni] = BHI_O + (uint32_t)row * 128;
        bSw[ni]   = (uint32_t)(row & 7);
    }
    const uint32_t a_c = (uint32_t)(l >> 4);
    const uint32_t b_c = (uint32_t)((l >> 3) & 1);

    float acc[4][4][4];
    #pragma unroll
    for (int i = 0; i < 4; ++i)
        #pragma unroll
        for (int j = 0; j < 4; ++j)
            #pragma unroll
            for (int q = 0; q < 4; ++q) acc[i][j][q] = 0.f;

    uint32_t Ah[2][4][4], Al[2][4][4], Bh[2][2][4], Bl[2][2][4];

    constexpr int NC = K_TOT / GBK;

    // prologue: fill stages 0 and 1 (chunks 0, 1)
    #pragma unroll
    for (int s = 0; s < 2; ++s) {
        const uint32_t sb = sbase + (uint32_t)s * STG_B;
        #pragma unroll
        for (int i = 0; i < 16; ++i)
            cpasync16(sb + (uint32_t)i * 4096 + s0,
                      pb[i >> 2] + (size_t)((i & 3) * 32) * K_TOT * 2 + (size_t)s * 128);
        cp_commit();
    }

    #pragma unroll 1
    for (int c = 0; c < NC; ++c) {
        cp_wait<1>();                // chunk c complete (issued 2 chunks ago)
        __syncthreads();             // visible to all warps

        // prefetch chunk c+2 into the slot vacated by chunk c-1
        const int pf = c + 2;
        if (pf < NC) {
            const uint32_t sbpf = sbase + (uint32_t)(pf % STAGES) * STG_B;
            #pragma unroll
            for (int i = 0; i < 16; ++i)
                cpasync16(sbpf + (uint32_t)i * 4096 + s0,
                          pb[i >> 2] + (size_t)((i & 3) * 32) * K_TOT * 2
                                     + (size_t)pf * 128);
        }
        cp_commit();

        const uint32_t sb = sbase + (uint32_t)(c % STAGES) * STG_B;
        LOAD_FRAGS(0, sb, 0);
        #pragma unroll
        for (int step = 0; step < 4; ++step) {
            if (step < 3) LOAD_FRAGS((step + 1) & 1, sb, step + 1);
            MMA_STEP(step & 1);
        }
    }

    // ---- epilogue -----------------------------------------------------------
    const int r_base = m0 + wm * 64 + (l >> 2);
    const int c_base = n0 + wn * 32 + (l & 3) * 2;
    #pragma unroll
    for (int mi = 0; mi < 4; ++mi) {
        #pragma unroll
        for (int nj = 0; nj < 4; ++nj) {
            const int col = c_base + nj * 8;
            const float bb0 = __ldg(bias + col);
            const float bb1 = __ldg(bias + col + 1);
            #pragma unroll
            for (int hh = 0; hh < 2; ++hh) {
                const int row = r_base + mi * 16 + hh * 8;
                float t0 = acc[mi][nj][hh * 2 + 0] + bb0;
                float t1 = acc[mi][nj][hh * 2 + 1] + bb1;
                if (FUSE1) {
                    t0 = 0.5f * t0 * (1.0f + erff(t0 * 0.70710678118654752f));
                    t1 = 0.5f * t1 * (1.0f + erff(t1 * 0.70710678118654752f));
                    __nv_bfloat16 h0, l0, h1, l1;
                    split_one(t0, h0, l0); split_one(t1, h1, l1);
                    uint32_t ph = ((uint32_t)__bfloat16_as_ushort(h1) << 16) | __bfloat16_as_ushort(h0);
                    uint32_t pl = ((uint32_t)__bfloat16_as_ushort(l1) << 16) | __bfloat16_as_ushort(l0);
                    *reinterpret_cast<uint32_t*>(OutHi + (size_t)row * Ncols + col) = ph;
                    *reinterpret_cast<uint32_t*>(OutLo + (size_t)row * Ncols + col) = pl;
                } else {
                    float2 o; o.x = t0; o.y = t1;
                    *reinterpret_cast<float2*>(OutF + (size_t)row * Ncols + col) = o;
                }
            }
        }
    }
}

// ---------------- launcher ----------------------------------------------------
extern "C" void kernel_launch(void* const* d_in, const int* in_sizes, int n_in,
                              void* d_out, int out_size) {
    (void)in_sizes; (void)n_in; (void)out_size;
    const float* X  = (const float*)d_in[0];
    const float* W1 = (const float*)d_in[1];
    const float* b1 = (const float*)d_in[2];
    const float* W2 = (const float*)d_in[3];
    const float* b2 = (const float*)d_in[4];
    float* out = (float*)d_out;

    __nv_bfloat16 *Xhi, *Xlo, *W1Thi, *W1Tlo, *W2Thi, *W2Tlo, *Thi, *Tlo;
    cudaGetSymbolAddress((void**)&Xhi,   g_Xhi);
    cudaGetSymbolAddress((void**)&Xlo,   g_Xlo);
    cudaGetSymbolAddress((void**)&W1Thi, g_W1Thi);
    cudaGetSymbolAddress((void**)&W1Tlo, g_W1Tlo);
    cudaGetSymbolAddress((void**)&W2Thi, g_W2Thi);
    cudaGetSymbolAddress((void**)&W2Tlo, g_W2Tlo);
    cudaGetSymbolAddress((void**)&Thi,   g_Thi);
    cudaGetSymbolAddress((void**)&Tlo,   g_Tlo);

    cudaFuncSetAttribute(hmma_gemm<D_SZ, true>,
                         cudaFuncAttributeMaxDynamicSharedMemorySize, SMEM_REQ);
    cudaFuncSetAttribute(hmma_gemm<H_SZ, false>,
                         cudaFuncAttributeMaxDynamicSharedMemorySize, SMEM_REQ);

    // 1) split X into hi/lo bf16
    split_kernel<<<4096, 256>>>(X, Xhi, Xlo, M_TOT * D_SZ / 4);
    // 2) transpose+split weights into K-major bf16
    transpose_split_kernel<<<dim3(H_SZ / 32, D_SZ / 32), dim3(32, 8)>>>(W1, W1Thi, W1Tlo, D_SZ, H_SZ);
    transpose_split_kernel<<<dim3(D_SZ / 32, H_SZ / 32), dim3(32, 8)>>>(W2, W2Thi, W2Tlo, H_SZ, D_SZ);
    // 3) GEMM1: T = GELU(X @ W1 + b1), split-bf16 output
    hmma_gemm<D_SZ, true><<<dim3(H_SZ / GBN, M_TOT / GBM), NTHR, SMEM_REQ>>>(
        Xhi, Xlo, W1Thi, W1Tlo, b1, Thi, Tlo, nullptr, H_SZ);
    // 4) GEMM2: out = T @ W2 + b2, fp32 output
    hmma_gemm<H_SZ, false><<<dim3(D_SZ / GBN, M_TOT / GBM), NTHR, SMEM_REQ>>>(
        Thi, Tlo, W2Thi, W2Tlo, b2, nullptr, nullptr, out, D_SZ);
    // 5) out[:,0,:] = X[:,0,:]
    copy_first_token_kernel<<<(B_SZ * D_SZ + 255) / 256, 256>>>(X, out);
}

// round 7
// speedup vs baseline: 1.8140x; 1.0166x over previous
#include <cuda_runtime.h>
#include <cuda_bf16.h>
#include <cstdint>
#include <math.h>

#define B_SZ 8
#define S_SZ 2048
#define D_SZ 1024
#define H_SZ 2048
#define M_TOT 16384

// ---------------- scratch (device globals) ------------------------------------
__device__ __nv_bfloat16 g_Xhi[(size_t)M_TOT * D_SZ];
__device__ __nv_bfloat16 g_Xlo[(size_t)M_TOT * D_SZ];
__device__ __nv_bfloat16 g_W1Thi[(size_t)H_SZ * D_SZ];   // [N=2048][K=1024]
__device__ __nv_bfloat16 g_W1Tlo[(size_t)H_SZ * D_SZ];
__device__ __nv_bfloat16 g_W2Thi[(size_t)D_SZ * H_SZ];   // [N=1024][K=2048]
__device__ __nv_bfloat16 g_W2Tlo[(size_t)D_SZ * H_SZ];
__device__ __nv_bfloat16 g_Thi[(size_t)M_TOT * H_SZ];
__device__ __nv_bfloat16 g_Tlo[(size_t)M_TOT * H_SZ];

// ---------------- small PTX helpers (sm_80-level, compute_103-safe) ------------
static __device__ __forceinline__ uint32_t smem_u32(const void* p) {
    uint32_t a;
    asm("{ .reg .u64 t; cvta.to.shared.u64 t, %1; cvt.u32.u64 %0, t; }"
        : "=r"(a) : "l"(p));
    return a;
}
static __device__ __forceinline__ void cpasync16(uint32_t dst, const void* src) {
    asm volatile("cp.async.cg.shared.global [%0], [%1], 16;"
                 :: "r"(dst), "l"(src) : "memory");
}
static __device__ __forceinline__ void cp_commit() {
    asm volatile("cp.async.commit_group;" ::: "memory");
}
template<int N>
static __device__ __forceinline__ void cp_wait() {
    asm volatile("cp.async.wait_group %0;" :: "n"(N) : "memory");
}
static __device__ __forceinline__ void ldsm4(uint32_t* r, uint32_t addr) {
    asm volatile("ldmatrix.sync.aligned.m8n8.x4.shared.b16 {%0,%1,%2,%3}, [%4];"
                 : "=r"(r[0]), "=r"(r[1]), "=r"(r[2]), "=r"(r[3]) : "r"(addr));
}
static __device__ __forceinline__ void mma16816(float* d, const uint32_t* a,
                                                uint32_t b0, uint32_t b1) {
    asm volatile(
        "mma.sync.aligned.m16n8k16.row.col.f32.bf16.bf16.f32 "
        "{%0,%1,%2,%3}, {%4,%5,%6,%7}, {%8,%9}, {%0,%1,%2,%3};"
        : "+f"(d[0]), "+f"(d[1]), "+f"(d[2]), "+f"(d[3])
        : "r"(a[0]), "r"(a[1]), "r"(a[2]), "r"(a[3]), "r"(b0), "r"(b1));
}

// ---------------- prep kernels ------------------------------------------------
static __device__ __forceinline__ void split_one(float x, __nv_bfloat16& h, __nv_bfloat16& l) {
    h = __float2bfloat16(x);
    l = __float2bfloat16(x - __bfloat162float(h));
}

__global__ void split_kernel(const float* __restrict__ X,
                             __nv_bfloat16* __restrict__ Hi,
                             __nv_bfloat16* __restrict__ Lo, int n4) {
    int stride = gridDim.x * blockDim.x;
    for (int i = blockIdx.x * blockDim.x + threadIdx.x; i < n4; i += stride) {
        float4 v = reinterpret_cast<const float4*>(X)[i];
        __nv_bfloat16 h0,h1,h2,h3,l0,l1,l2,l3;
        split_one(v.x,h0,l0); split_one(v.y,h1,l1);
        split_one(v.z,h2,l2); split_one(v.w,h3,l3);
        uint2 ph, pl;
        ph.x = ((uint32_t)__bfloat16_as_ushort(h1) << 16) | __bfloat16_as_ushort(h0);
        ph.y = ((uint32_t)__bfloat16_as_ushort(h3) << 16) | __bfloat16_as_ushort(h2);
        pl.x = ((uint32_t)__bfloat16_as_ushort(l1) << 16) | __bfloat16_as_ushort(l0);
        pl.y = ((uint32_t)__bfloat16_as_ushort(l3) << 16) | __bfloat16_as_ushort(l2);
        reinterpret_cast<uint2*>(Hi)[i] = ph;
        reinterpret_cast<uint2*>(Lo)[i] = pl;
    }
}

// W [R][C] fp32 -> WT_hi/lo [C][R] bf16
__global__ void transpose_split_kernel(const float* __restrict__ W,
                                       __nv_bfloat16* __restrict__ Thi,
                                       __nv_bfloat16* __restrict__ Tlo,
                                       int R, int C) {
    __shared__ float t[32][33];
    int c0 = blockIdx.x * 32, r0 = blockIdx.y * 32;
    int tx = threadIdx.x, ty = threadIdx.y;
    #pragma unroll
    for (int i = ty; i < 32; i += 8)
        t[i][tx] = W[(size_t)(r0 + i) * C + c0 + tx];
    __syncthreads();
    #pragma unroll
    for (int i = ty; i < 32; i += 8) {
        float x = t[tx][i];                 // = W[r0+tx][c0+i]
        __nv_bfloat16 h, l; split_one(x, h, l);
        size_t o = (size_t)(c0 + i) * R + r0 + tx;
        Thi[o] = h; Tlo[o] = l;
    }
}

__global__ void copy_first_token_kernel(const float* __restrict__ X,
                                        float* __restrict__ out) {
    int i = blockIdx.x * blockDim.x + threadIdx.x;
    if (i >= B_SZ * D_SZ) return;
    int b = i >> 10, d = i & 1023;
    size_t off = ((size_t)b * S_SZ) * D_SZ + d;
    out[off] = X[off];
}

// ---------------- HMMA (mma.sync) split-bf16 GEMM -----------------------------
// C[M,N] = act(A·B^T + bias); A [M][K] hi/lo, B [N][K] hi/lo (K-major).
// CTA tile 128x128x32, 3-stage cp.async (96KB), 4 warps of 64x64, 2 CTAs/SM.
#define GBM 128
#define GBN 128
#define GBK 32
#define NTHR 128
#define STAGES 3
#define STG_B 32768                 // Ahi 8K | Alo 8K | Bhi 8K | Blo 8K
#define AHI_O 0
#define ALO_O 8192
#define BHI_O 16384
#define BLO_O 24576
#define SMEM_REQ (STAGES * STG_B)   // 96KB

#define LOAD_FRAGS(SB, STEP) do {                                              \
    const uint32_t acx = (uint32_t)((STEP) * 2) + a_c;                         \
    const uint32_t bcx = (uint32_t)((STEP) * 2) + b_c;                         \
    _Pragma("unroll")                                                          \
    for (int mi_ = 0; mi_ < 4; ++mi_) {                                        \
        uint32_t ad = (SB) + aAddr[mi_] + ((acx ^ aSw[mi_]) << 4);             \
        ldsm4(Ah[mi_], ad);                                                    \
        ldsm4(Al[mi_], ad + (ALO_O - AHI_O));                                  \
    }                                                                          \
    _Pragma("unroll")                                                          \
    for (int ni_ = 0; ni_ < 4; ++ni_) {                                        \
        uint32_t bd = (SB) + bAddr[ni_] + ((bcx ^ bSw[ni_]) << 4);             \
        ldsm4(Bh[ni_], bd);                                                    \
        ldsm4(Bl[ni_], bd + (BLO_O - BHI_O));                                  \
    }                                                                          \
} while (0)

#define MMA_STEP() do {                                                        \
    _Pragma("unroll")                                                          \
    for (int mi_ = 0; mi_ < 4; ++mi_) {                                        \
        _Pragma("unroll")                                                      \
        for (int nj_ = 0; nj_ < 8; ++nj_) {                                    \
            const int ni_ = nj_ >> 1, h_ = (nj_ & 1) * 2;                      \
            mma16816(acc[mi_][nj_], Ah[mi_], Bh[ni_][h_], Bh[ni_][h_ + 1]);    \
            mma16816(acc[mi_][nj_], Ah[mi_], Bl[ni_][h_], Bl[ni_][h_ + 1]);    \
            mma16816(acc[mi_][nj_], Al[mi_], Bh[ni_][h_], Bh[ni_][h_ + 1]);    \
        }                                                                      \
    }                                                                          \
} while (0)

template<int K_TOT, bool FUSE1>
__global__ __launch_bounds__(NTHR, 2)
void hmma_gemm(const __nv_bfloat16* __restrict__ Ahi,
               const __nv_bfloat16* __restrict__ Alo,
               const __nv_bfloat16* __restrict__ Bhi,
               const __nv_bfloat16* __restrict__ Blo,
               const float* __restrict__ bias,
               __nv_bfloat16* __restrict__ OutHi,
               __nv_bfloat16* __restrict__ OutLo,
               float* __restrict__ OutF,
               int Ncols)
{
    extern __shared__ char smem_raw[];
    const uint32_t sbase = smem_u32(smem_raw);

    const int tid = threadIdx.x;
    const int wid = tid >> 5;
    const int l   = tid & 31;
    const int m0  = blockIdx.y * GBM;
    const int n0  = blockIdx.x * GBN;
    const int wm  = wid & 1;        // 2 warp-rows of 64
    const int wn  = wid >> 1;       // 2 warp-cols of 64

    // ---- global->smem load plan: 16 x 16B units per thread ------------------
    // unit i: mat = i>>2, row = (i&3)*32 + (tid>>2), 16B-chunk = tid&3
    const char* pbA[2];
    const char* pbB[2];
    {
        const int r0 = tid >> 2, cc = tid & 3;
        pbA[0] = (const char*)(Ahi + (size_t)(m0 + r0) * K_TOT) + cc * 16;
        pbA[1] = (const char*)(Alo + (size_t)(m0 + r0) * K_TOT) + cc * 16;
        pbB[0] = (const char*)(Bhi + (size_t)(n0 + r0) * K_TOT) + cc * 16;
        pbB[1] = (const char*)(Blo + (size_t)(n0 + r0) * K_TOT) + cc * 16;
    }
    // smem offset for unit i: i*2048 + s0 ; swizzle chunk' = c ^ ((row>>1)&3)
    const uint32_t s0 = (uint32_t)((tid >> 2) * 64)
                      + ((uint32_t)((tid & 3) ^ ((tid >> 3) & 3)) << 4);

    // ---- ldmatrix address pieces -------------------------------------------
    uint32_t aAddr[4], aSw[4], bAddr[4], bSw[4];
    #pragma unroll
    for (int mi = 0; mi < 4; ++mi) {
        int row = wm * 64 + mi * 16 + ((l >> 3) & 1) * 8 + (l & 7);
        aAddr[mi] = AHI_O + (uint32_t)row * 64;
        aSw[mi]   = (uint32_t)((row >> 1) & 3);
    }
    #pragma unroll
    for (int ni = 0; ni < 4; ++ni) {
        int row = wn * 64 + ni * 16 + ((l >> 4) & 1) * 8 + (l & 7);
        bAddr[ni] = BHI_O + (uint32_t)row * 64;
        bSw[ni]   = (uint32_t)((row >> 1) & 3);
    }
    const uint32_t a_c = (uint32_t)(l >> 4);
    const uint32_t b_c = (uint32_t)((l >> 3) & 1);

    float acc[4][8][4];
    #pragma unroll
    for (int i = 0; i < 4; ++i)
        #pragma unroll
        for (int j = 0; j < 8; ++j)
            #pragma unroll
            for (int q = 0; q < 4; ++q) acc[i][j][q] = 0.f;

    uint32_t Ah[4][4], Al[4][4], Bh[4][4], Bl[4][4];

    constexpr int NC = K_TOT / GBK;

    // prologue: fill stages 0 and 1 (chunks 0, 1)
    #pragma unroll
    for (int s = 0; s < 2; ++s) {
        const uint32_t sb = sbase + (uint32_t)s * STG_B;
        #pragma unroll
        for (int i = 0; i < 16; ++i) {
            const char* p = (i < 8 ? pbA[(i >> 2) & 1] : pbB[(i >> 2) & 1])
                          + (size_t)((i & 3) * 32) * K_TOT * 2 + (size_t)s * 64;
            cpasync16(sb + (uint32_t)i * 2048 + s0, p);
        }
        cp_commit();
    }

    #pragma unroll 1
    for (int c = 0; c < NC; ++c) {
        cp_wait<1>();                // chunk c complete (issued 2 chunks ago)
        __syncthreads();

        // prefetch chunk c+2 into the slot vacated by chunk c-1
        const int pf = c + 2;
        if (pf < NC) {
            const uint32_t sbpf = sbase + (uint32_t)(pf % STAGES) * STG_B;
            #pragma unroll
            for (int i = 0; i < 16; ++i) {
                const char* p = (i < 8 ? pbA[(i >> 2) & 1] : pbB[(i >> 2) & 1])
                              + (size_t)((i & 3) * 32) * K_TOT * 2 + (size_t)pf * 64;
                cpasync16(sbpf + (uint32_t)i * 2048 + s0, p);
            }
        }
        cp_commit();

        const uint32_t sb = sbase + (uint32_t)(c % STAGES) * STG_B;
        #pragma unroll
        for (int step = 0; step < 2; ++step) {
            LOAD_FRAGS(sb, step);
            MMA_STEP();
        }
    }

    // ---- epilogue -----------------------------------------------------------
    const int r_base = m0 + wm * 64 + (l >> 2);
    const int c_base = n0 + wn * 64 + (l & 3) * 2;
    #pragma unroll
    for (int mi = 0; mi < 4; ++mi) {
        #pragma unroll
        for (int nj = 0; nj < 8; ++nj) {
            const int col = c_base + nj * 8;
            const float bb0 = __ldg(bias + col);
            const float bb1 = __ldg(bias + col + 1);
            #pragma unroll
            for (int hh = 0; hh < 2; ++hh) {
                const int row = r_base + mi * 16 + hh * 8;
                float t0 = acc[mi][nj][hh * 2 + 0] + bb0;
                float t1 = acc[mi][nj][hh * 2 + 1] + bb1;
                if (FUSE1) {
                    t0 = 0.5f * t0 * (1.0f + erff(t0 * 0.70710678118654752f));
                    t1 = 0.5f * t1 * (1.0f + erff(t1 * 0.70710678118654752f));
                    __nv_bfloat16 h0, l0, h1, l1;
                    split_one(t0, h0, l0); split_one(t1, h1, l1);
                    uint32_t ph = ((uint32_t)__bfloat16_as_ushort(h1) << 16) | __bfloat16_as_ushort(h0);
                    uint32_t pl = ((uint32_t)__bfloat16_as_ushort(l1) << 16) | __bfloat16_as_ushort(l0);
                    *reinterpret_cast<uint32_t*>(OutHi + (size_t)row * Ncols + col) = ph;
                    *reinterpret_cast<uint32_t*>(OutLo + (size_t)row * Ncols + col) = pl;
                } else {
                    float2 o; o.x = t0; o.y = t1;
                    *reinterpret_cast<float2*>(OutF + (size_t)row * Ncols + col) = o;
                }
            }
        }
    }
}

// ---------------- launcher ----------------------------------------------------
extern "C" void kernel_launch(void* const* d_in, const int* in_sizes, int n_in,
                              void* d_out, int out_size) {
    (void)in_sizes; (void)n_in; (void)out_size;
    const float* X  = (const float*)d_in[0];
    const float* W1 = (const float*)d_in[1];
    const float* b1 = (const float*)d_in[2];
    const float* W2 = (const float*)d_in[3];
    const float* b2 = (const float*)d_in[4];
    float* out = (float*)d_out;

    __nv_bfloat16 *Xhi, *Xlo, *W1Thi, *W1Tlo, *W2Thi, *W2Tlo, *Thi, *Tlo;
    cudaGetSymbolAddress((void**)&Xhi,   g_Xhi);
    cudaGetSymbolAddress((void**)&Xlo,   g_Xlo);
    cudaGetSymbolAddress((void**)&W1Thi, g_W1Thi);
    cudaGetSymbolAddress((void**)&W1Tlo, g_W1Tlo);
    cudaGetSymbolAddress((void**)&W2Thi, g_W2Thi);
    cudaGetSymbolAddress((void**)&W2Tlo, g_W2Tlo);
    cudaGetSymbolAddress((void**)&Thi,   g_Thi);
    cudaGetSymbolAddress((void**)&Tlo,   g_Tlo);

    cudaFuncSetAttribute(hmma_gemm<D_SZ, true>,
                         cudaFuncAttributeMaxDynamicSharedMemorySize, SMEM_REQ);
    cudaFuncSetAttribute(hmma_gemm<H_SZ, false>,
                         cudaFuncAttributeMaxDynamicSharedMemorySize, SMEM_REQ);

    // 1) split X into hi/lo bf16
    split_kernel<<<4096, 256>>>(X, Xhi, Xlo, M_TOT * D_SZ / 4);
    // 2) transpose+split weights into K-major bf16
    transpose_split_kernel<<<dim3(H_SZ / 32, D_SZ / 32), dim3(32, 8)>>>(W1, W1Thi, W1Tlo, D_SZ, H_SZ);
    transpose_split_kernel<<<dim3(D_SZ / 32, H_SZ / 32), dim3(32, 8)>>>(W2, W2Thi, W2Tlo, H_SZ, D_SZ);
    // 3) GEMM1: T = GELU(X @ W1 + b1), split-bf16 output
    hmma_gemm<D_SZ, true><<<dim3(H_SZ / GBN, M_TOT / GBM), NTHR, SMEM_REQ>>>(
        Xhi, Xlo, W1Thi, W1Tlo, b1, Thi, Tlo, nullptr, H_SZ);
    // 4) GEMM2: out = T @ W2 + b2, fp32 output
    hmma_gemm<H_SZ, false><<<dim3(D_SZ / GBN, M_TOT / GBM), NTHR, SMEM_REQ>>>(
        Thi, Tlo, W2Thi, W2Tlo, b2, nullptr, nullptr, out, D_SZ);
    // 5) out[:,0,:] = X[:,0,:]
    copy_first_token_kernel<<<(B_SZ * D_SZ + 255) / 256, 256>>>(X, out);
}

// round 8
// speedup vs baseline: 2.3938x; 1.3197x over previous
#include <cuda_runtime.h>
#include <cuda_fp16.h>
#include <cstdint>
#include <math.h>

#define B_SZ 8
#define S_SZ 2048
#define D_SZ 1024
#define H_SZ 2048
#define M_TOT 16384

// ---------------- scratch (device globals) ------------------------------------
__device__ __half g_Xhi[(size_t)M_TOT * D_SZ];
__device__ __half g_Xlo[(size_t)M_TOT * D_SZ];
__device__ __half g_W1T[(size_t)H_SZ * D_SZ];    // [N=2048][K=1024] fp16
__device__ __half g_W2T[(size_t)D_SZ * H_SZ];    // [N=1024][K=2048] fp16
__device__ __half g_Thi[(size_t)M_TOT * H_SZ];
__device__ __half g_Tlo[(size_t)M_TOT * H_SZ];

// ---------------- small PTX helpers (sm_80-level, compute_103-safe) ------------
static __device__ __forceinline__ uint32_t smem_u32(const void* p) {
    uint32_t a;
    asm("{ .reg .u64 t; cvta.to.shared.u64 t, %1; cvt.u32.u64 %0, t; }"
        : "=r"(a) : "l"(p));
    return a;
}
static __device__ __forceinline__ void cpasync16(uint32_t dst, const void* src) {
    asm volatile("cp.async.cg.shared.global [%0], [%1], 16;"
                 :: "r"(dst), "l"(src) : "memory");
}
static __device__ __forceinline__ void cp_commit() {
    asm volatile("cp.async.commit_group;" ::: "memory");
}
template<int N>
static __device__ __forceinline__ void cp_wait() {
    asm volatile("cp.async.wait_group %0;" :: "n"(N) : "memory");
}
static __device__ __forceinline__ void ldsm4(uint32_t* r, uint32_t addr) {
    asm volatile("ldmatrix.sync.aligned.m8n8.x4.shared.b16 {%0,%1,%2,%3}, [%4];"
                 : "=r"(r[0]), "=r"(r[1]), "=r"(r[2]), "=r"(r[3]) : "r"(addr));
}
static __device__ __forceinline__ void mma16816(float* d, const uint32_t* a,
                                                uint32_t b0, uint32_t b1) {
    asm volatile(
        "mma.sync.aligned.m16n8k16.row.col.f32.f16.f16.f32 "
        "{%0,%1,%2,%3}, {%4,%5,%6,%7}, {%8,%9}, {%0,%1,%2,%3};"
        : "+f"(d[0]), "+f"(d[1]), "+f"(d[2]), "+f"(d[3])
        : "r"(a[0]), "r"(a[1]), "r"(a[2]), "r"(a[3]), "r"(b0), "r"(b1));
}

// ---------------- prep kernels ------------------------------------------------
static __device__ __forceinline__ void split_one(float x, __half& h, __half& l) {
    h = __float2half_rn(x);
    l = __float2half_rn(x - __half2float(h));
}

__global__ void split_kernel(const float* __restrict__ X,
                             __half* __restrict__ Hi,
                             __half* __restrict__ Lo, int n4) {
    int stride = gridDim.x * blockDim.x;
    for (int i = blockIdx.x * blockDim.x + threadIdx.x; i < n4; i += stride) {
        float4 v = reinterpret_cast<const float4*>(X)[i];
        __half h0,h1,h2,h3,l0,l1,l2,l3;
        split_one(v.x,h0,l0); split_one(v.y,h1,l1);
        split_one(v.z,h2,l2); split_one(v.w,h3,l3);
        uint2 ph, pl;
        ph.x = ((uint32_t)__half_as_ushort(h1) << 16) | __half_as_ushort(h0);
        ph.y = ((uint32_t)__half_as_ushort(h3) << 16) | __half_as_ushort(h2);
        pl.x = ((uint32_t)__half_as_ushort(l1) << 16) | __half_as_ushort(l0);
        pl.y = ((uint32_t)__half_as_ushort(l3) << 16) | __half_as_ushort(l2);
        reinterpret_cast<uint2*>(Hi)[i] = ph;
        reinterpret_cast<uint2*>(Lo)[i] = pl;
    }
}

// W [R][C] fp32 -> WT [C][R] fp16 (single precision level)
__global__ void transpose_half_kernel(const float* __restrict__ W,
                                      __half* __restrict__ T,
                                      int R, int C) {
    __shared__ float t[32][33];
    int c0 = blockIdx.x * 32, r0 = blockIdx.y * 32;
    int tx = threadIdx.x, ty = threadIdx.y;
    #pragma unroll
    for (int i = ty; i < 32; i += 8)
        t[i][tx] = W[(size_t)(r0 + i) * C + c0 + tx];
    __syncthreads();
    #pragma unroll
    for (int i = ty; i < 32; i += 8) {
        float x = t[tx][i];                 // = W[r0+tx][c0+i]
        T[(size_t)(c0 + i) * R + r0 + tx] = __float2half_rn(x);
    }
}

__global__ void copy_first_token_kernel(const float* __restrict__ X,
                                        float* __restrict__ out) {
    int i = blockIdx.x * blockDim.x + threadIdx.x;
    if (i >= B_SZ * D_SZ) return;
    int b = i >> 10, d = i & 1023;
    size_t off = ((size_t)b * S_SZ) * D_SZ + d;
    out[off] = X[off];
}

// ---------------- HMMA (mma.sync) split-fp16 GEMM ------------------------------
// C[M,N] = act((Ahi+Alo)·B^T + bias); A split fp16, B single fp16 (K-major).
// CTA tile 128x128x32, 3-stage cp.async (72KB), 4 warps of 64x64, 2 CTAs/SM.
#define GBM 128
#define GBN 128
#define GBK 32
#define NTHR 128
#define STAGES 3
#define STG_B 24576                 // Ahi 8K | Alo 8K | B 8K
#define AHI_O 0
#define ALO_O 8192
#define B_O   16384
#define SMEM_REQ (STAGES * STG_B)   // 72KB

#define LOAD_FRAGS(SB, STEP) do {                                              \
    const uint32_t acx = (uint32_t)((STEP) * 2) + a_c;                         \
    const uint32_t bcx = (uint32_t)((STEP) * 2) + b_c;                         \
    _Pragma("unroll")                                                          \
    for (int mi_ = 0; mi_ < 4; ++mi_) {                                        \
        uint32_t ad = (SB) + aAddr[mi_] + ((acx ^ aSw[mi_]) << 4);             \
        ldsm4(Ah[mi_], ad);                                                    \
        ldsm4(Al[mi_], ad + (ALO_O - AHI_O));                                  \
    }                                                                          \
    _Pragma("unroll")                                                          \
    for (int ni_ = 0; ni_ < 4; ++ni_) {                                        \
        uint32_t bd = (SB) + bAddr[ni_] + ((bcx ^ bSw[ni_]) << 4);             \
        ldsm4(Bh[ni_], bd);                                                    \
    }                                                                          \
} while (0)

#define MMA_STEP() do {                                                        \
    _Pragma("unroll")                                                          \
    for (int mi_ = 0; mi_ < 4; ++mi_) {                                        \
        _Pragma("unroll")                                                      \
        for (int nj_ = 0; nj_ < 8; ++nj_) {                                    \
            const int ni_ = nj_ >> 1, h_ = (nj_ & 1) * 2;                      \
            mma16816(acc[mi_][nj_], Ah[mi_], Bh[ni_][h_], Bh[ni_][h_ + 1]);    \
            mma16816(acc[mi_][nj_], Al[mi_], Bh[ni_][h_], Bh[ni_][h_ + 1]);    \
        }                                                                      \
    }                                                                          \
} while (0)

template<int K_TOT, bool FUSE1>
__global__ __launch_bounds__(NTHR, 2)
void hmma_gemm(const __half* __restrict__ Ahi,
               const __half* __restrict__ Alo,
               const __half* __restrict__ Bmat,
               const float* __restrict__ bias,
               __half* __restrict__ OutHi,
               __half* __restrict__ OutLo,
               float* __restrict__ OutF,
               int Ncols)
{
    extern __shared__ char smem_raw[];
    const uint32_t sbase = smem_u32(smem_raw);

    const int tid = threadIdx.x;
    const int wid = tid >> 5;
    const int l   = tid & 31;
    const int m0  = blockIdx.y * GBM;
    const int n0  = blockIdx.x * GBN;
    const int wm  = wid & 1;        // 2 warp-rows of 64
    const int wn  = wid >> 1;       // 2 warp-cols of 64

    // ---- global->smem load plan: 12 x 16B units per thread ------------------
    // unit i (0..11): mat = i>>2 (0=Ahi,1=Alo,2=B), row = (i&3)*32 + (tid>>2)
    const char* pm[3];
    {
        const int r0 = tid >> 2, cc = tid & 3;
        pm[0] = (const char*)(Ahi  + (size_t)(m0 + r0) * K_TOT) + cc * 16;
        pm[1] = (const char*)(Alo  + (size_t)(m0 + r0) * K_TOT) + cc * 16;
        pm[2] = (const char*)(Bmat + (size_t)(n0 + r0) * K_TOT) + cc * 16;
    }
    // smem offset for unit i: i*2048 + s0 ; swizzle chunk' = c ^ ((row>>1)&3)
    const uint32_t s0 = (uint32_t)((tid >> 2) * 64)
                      + ((uint32_t)((tid & 3) ^ ((tid >> 3) & 3)) << 4);

    // ---- ldmatrix address pieces -------------------------------------------
    uint32_t aAddr[4], aSw[4], bAddr[4], bSw[4];
    #pragma unroll
    for (int mi = 0; mi < 4; ++mi) {
        int row = wm * 64 + mi * 16 + ((l >> 3) & 1) * 8 + (l & 7);
        aAddr[mi] = AHI_O + (uint32_t)row * 64;
        aSw[mi]   = (uint32_t)((row >> 1) & 3);
    }
    #pragma unroll
    for (int ni = 0; ni < 4; ++ni) {
        int row = wn * 64 + ni * 16 + ((l >> 4) & 1) * 8 + (l & 7);
        bAddr[ni] = B_O + (uint32_t)row * 64;
        bSw[ni]   = (uint32_t)((row >> 1) & 3);
    }
    const uint32_t a_c = (uint32_t)(l >> 4);
    const uint32_t b_c = (uint32_t)((l >> 3) & 1);

    float acc[4][8][4];
    #pragma unroll
    for (int i = 0; i < 4; ++i)
        #pragma unroll
        for (int j = 0; j < 8; ++j)
            #pragma unroll
            for (int q = 0; q < 4; ++q) acc[i][j][q] = 0.f;

    uint32_t Ah[4][4], Al[4][4], Bh[4][4];

    constexpr int NC = K_TOT / GBK;

    // prologue: fill stages 0 and 1 (chunks 0, 1)
    #pragma unroll
    for (int s = 0; s < 2; ++s) {
        const uint32_t sb = sbase + (uint32_t)s * STG_B;
        #pragma unroll
        for (int i = 0; i < 12; ++i) {
            const char* p = pm[i >> 2]
                          + (size_t)((i & 3) * 32) * K_TOT * 2 + (size_t)s * 64;
            cpasync16(sb + (uint32_t)i * 2048 + s0, p);
        }
        cp_commit();
    }

    #pragma unroll 1
    for (int c = 0; c < NC; ++c) {
        cp_wait<1>();                // chunk c complete (issued 2 chunks ago)
        __syncthreads();

        // prefetch chunk c+2 into the slot vacated by chunk c-1
        const int pf = c + 2;
        if (pf < NC) {
            const uint32_t sbpf = sbase + (uint32_t)(pf % STAGES) * STG_B;
            #pragma unroll
            for (int i = 0; i < 12; ++i) {
                const char* p = pm[i >> 2]
                              + (size_t)((i & 3) * 32) * K_TOT * 2 + (size_t)pf * 64;
                cpasync16(sbpf + (uint32_t)i * 2048 + s0, p);
            }
        }
        cp_commit();

        const uint32_t sb = sbase + (uint32_t)(c % STAGES) * STG_B;
        #pragma unroll
        for (int step = 0; step < 2; ++step) {
            LOAD_FRAGS(sb, step);
            MMA_STEP();
        }
    }

    // ---- epilogue -----------------------------------------------------------
    const int r_base = m0 + wm * 64 + (l >> 2);
    const int c_base = n0 + wn * 64 + (l & 3) * 2;
    #pragma unroll
    for (int mi = 0; mi < 4; ++mi) {
        #pragma unroll
        for (int nj = 0; nj < 8; ++nj) {
            const int col = c_base + nj * 8;
            const float bb0 = __ldg(bias + col);
            const float bb1 = __ldg(bias + col + 1);
            #pragma unroll
            for (int hh = 0; hh < 2; ++hh) {
                const int row = r_base + mi * 16 + hh * 8;
                float t0 = acc[mi][nj][hh * 2 + 0] + bb0;
                float t1 = acc[mi][nj][hh * 2 + 1] + bb1;
                if (FUSE1) {
                    t0 = 0.5f * t0 * (1.0f + erff(t0 * 0.70710678118654752f));
                    t1 = 0.5f * t1 * (1.0f + erff(t1 * 0.70710678118654752f));
                    __half h0, l0, h1, l1;
                    split_one(t0, h0, l0); split_one(t1, h1, l1);
                    uint32_t ph = ((uint32_t)__half_as_ushort(h1) << 16) | __half_as_ushort(h0);
                    uint32_t pl = ((uint32_t)__half_as_ushort(l1) << 16) | __half_as_ushort(l0);
                    *reinterpret_cast<uint32_t*>(OutHi + (size_t)row * Ncols + col) = ph;
                    *reinterpret_cast<uint32_t*>(OutLo + (size_t)row * Ncols + col) = pl;
                } else {
                    float2 o; o.x = t0; o.y = t1;
                    *reinterpret_cast<float2*>(OutF + (size_t)row * Ncols + col) = o;
                }
            }
        }
    }
}

// ---------------- launcher ----------------------------------------------------
extern "C" void kernel_launch(void* const* d_in, const int* in_sizes, int n_in,
                              void* d_out, int out_size) {
    (void)in_sizes; (void)n_in; (void)out_size;
    const float* X  = (const float*)d_in[0];
    const float* W1 = (const float*)d_in[1];
    const float* b1 = (const float*)d_in[2];
    const float* W2 = (const float*)d_in[3];
    const float* b2 = (const float*)d_in[4];
    float* out = (float*)d_out;

    __half *Xhi, *Xlo, *W1T, *W2T, *Thi, *Tlo;
    cudaGetSymbolAddress((void**)&Xhi, g_Xhi);
    cudaGetSymbolAddress((void**)&Xlo, g_Xlo);
    cudaGetSymbolAddress((void**)&W1T, g_W1T);
    cudaGetSymbolAddress((void**)&W2T, g_W2T);
    cudaGetSymbolAddress((void**)&Thi, g_Thi);
    cudaGetSymbolAddress((void**)&Tlo, g_Tlo);

    cudaFuncSetAttribute(hmma_gemm<D_SZ, true>,
                         cudaFuncAttributeMaxDynamicSharedMemorySize, SMEM_REQ);
    cudaFuncSetAttribute(hmma_gemm<H_SZ, false>,
                         cudaFuncAttributeMaxDynamicSharedMemorySize, SMEM_REQ);

    // 1) split X into hi/lo fp16
    split_kernel<<<4096, 256>>>(X, Xhi, Xlo, M_TOT * D_SZ / 4);
    // 2) transpose weights into K-major single fp16
    transpose_half_kernel<<<dim3(H_SZ / 32, D_SZ / 32), dim3(32, 8)>>>(W1, W1T, D_SZ, H_SZ);
    transpose_half_kernel<<<dim3(D_SZ / 32, H_SZ / 32), dim3(32, 8)>>>(W2, W2T, H_SZ, D_SZ);
    // 3) GEMM1: T = GELU(X @ W1 + b1), split-fp16 output
    hmma_gemm<D_SZ, true><<<dim3(H_SZ / GBN, M_TOT / GBM), NTHR, SMEM_REQ>>>(
        Xhi, Xlo, W1T, b1, Thi, Tlo, nullptr, H_SZ);
    // 4) GEMM2: out = T @ W2 + b2, fp32 output
    hmma_gemm<H_SZ, false><<<dim3(D_SZ / GBN, M_TOT / GBM), NTHR, SMEM_REQ>>>(
        Thi, Tlo, W2T, b2, nullptr, nullptr, out, D_SZ);
    // 5) out[:,0,:] = X[:,0,:]
    copy_first_token_kernel<<<(B_SZ * D_SZ + 255) / 256, 256>>>(X, out);
}

// round 9
// speedup vs baseline: 2.6899x; 1.1237x over previous
#include <cuda_runtime.h>
#include <cuda_fp16.h>
#include <cstdint>
#include <math.h>

#define B_SZ 8
#define S_SZ 2048
#define D_SZ 1024
#define H_SZ 2048
#define M_TOT 16384

// ---------------- scratch (device globals) ------------------------------------
__device__ __half g_Xhi[(size_t)M_TOT * D_SZ];
__device__ __half g_Xlo[(size_t)M_TOT * D_SZ];
__device__ __half g_W1T[(size_t)H_SZ * D_SZ];    // [N=2048][K=1024] fp16
__device__ __half g_W2T[(size_t)D_SZ * H_SZ];    // [N=1024][K=2048] fp16
__device__ __half g_Thi[(size_t)M_TOT * H_SZ];
__device__ __half g_Tlo[(size_t)M_TOT * H_SZ];

// ---------------- small PTX helpers (sm_80-level, compute_103-safe) ------------
static __device__ __forceinline__ uint32_t smem_u32(const void* p) {
    uint32_t a;
    asm("{ .reg .u64 t; cvta.to.shared.u64 t, %1; cvt.u32.u64 %0, t; }"
        : "=r"(a) : "l"(p));
    return a;
}
static __device__ __forceinline__ void cpasync16(uint32_t dst, const void* src) {
    asm volatile("cp.async.cg.shared.global [%0], [%1], 16;"
                 :: "r"(dst), "l"(src) : "memory");
}
static __device__ __forceinline__ void cp_commit() {
    asm volatile("cp.async.commit_group;" ::: "memory");
}
template<int N>
static __device__ __forceinline__ void cp_wait() {
    asm volatile("cp.async.wait_group %0;" :: "n"(N) : "memory");
}
static __device__ __forceinline__ void ldsm4(uint32_t* r, uint32_t addr) {
    asm volatile("ldmatrix.sync.aligned.m8n8.x4.shared.b16 {%0,%1,%2,%3}, [%4];"
                 : "=r"(r[0]), "=r"(r[1]), "=r"(r[2]), "=r"(r[3]) : "r"(addr));
}
static __device__ __forceinline__ void mma16816(float* d, const uint32_t* a,
                                                uint32_t b0, uint32_t b1) {
    asm volatile(
        "mma.sync.aligned.m16n8k16.row.col.f32.f16.f16.f32 "
        "{%0,%1,%2,%3}, {%4,%5,%6,%7}, {%8,%9}, {%0,%1,%2,%3};"
        : "+f"(d[0]), "+f"(d[1]), "+f"(d[2]), "+f"(d[3])
        : "r"(a[0]), "r"(a[1]), "r"(a[2]), "r"(a[3]), "r"(b0), "r"(b1));
}

// ---------------- prep kernels ------------------------------------------------
static __device__ __forceinline__ void split_one(float x, __half& h, __half& l) {
    h = __float2half_rn(x);
    l = __float2half_rn(x - __half2float(h));
}

__global__ void split_kernel(const float* __restrict__ X,
                             __half* __restrict__ Hi,
                             __half* __restrict__ Lo, int n4) {
    int stride = gridDim.x * blockDim.x;
    for (int i = blockIdx.x * blockDim.x + threadIdx.x; i < n4; i += stride) {
        float4 v = reinterpret_cast<const float4*>(X)[i];
        __half h0,h1,h2,h3,l0,l1,l2,l3;
        split_one(v.x,h0,l0); split_one(v.y,h1,l1);
        split_one(v.z,h2,l2); split_one(v.w,h3,l3);
        uint2 ph, pl;
        ph.x = ((uint32_t)__half_as_ushort(h1) << 16) | __half_as_ushort(h0);
        ph.y = ((uint32_t)__half_as_ushort(h3) << 16) | __half_as_ushort(h2);
        pl.x = ((uint32_t)__half_as_ushort(l1) << 16) | __half_as_ushort(l0);
        pl.y = ((uint32_t)__half_as_ushort(l3) << 16) | __half_as_ushort(l2);
        reinterpret_cast<uint2*>(Hi)[i] = ph;
        reinterpret_cast<uint2*>(Lo)[i] = pl;
    }
}

// W [R][C] fp32 -> WT [C][R] fp16
__global__ void transpose_half_kernel(const float* __restrict__ W,
                                      __half* __restrict__ T,
                                      int R, int C) {
    __shared__ float t[32][33];
    int c0 = blockIdx.x * 32, r0 = blockIdx.y * 32;
    int tx = threadIdx.x, ty = threadIdx.y;
    #pragma unroll
    for (int i = ty; i < 32; i += 8)
        t[i][tx] = W[(size_t)(r0 + i) * C + c0 + tx];
    __syncthreads();
    #pragma unroll
    for (int i = ty; i < 32; i += 8) {
        float x = t[tx][i];                 // = W[r0+tx][c0+i]
        T[(size_t)(c0 + i) * R + r0 + tx] = __float2half_rn(x);
    }
}

__global__ void copy_first_token_kernel(const float* __restrict__ X,
                                        float* __restrict__ out) {
    int i = blockIdx.x * blockDim.x + threadIdx.x;
    if (i >= B_SZ * D_SZ) return;
    int b = i >> 10, d = i & 1023;
    size_t off = ((size_t)b * S_SZ) * D_SZ + d;
    out[off] = X[off];
}

// ---------------- HMMA (mma.sync) split-fp16 GEMM ------------------------------
// C[M,N] = act((Ahi+Alo)·B^T + bias); A split fp16, B single fp16 (K-major).
// CTA tile 64x128x32, 3-stage cp.async (48KB), 4 warps of 32x64, 4 CTAs/SM.
#define GBM 64
#define GBN 128
#define GBK 32
#define NTHR 128
#define STAGES 3
#define STG_B 16384                 // Ahi 4K | Alo 4K | B 8K
#define AHI_O 0
#define ALO_O 4096
#define B_O   8192
#define SMEM_REQ (STAGES * STG_B)   // 48KB

#define LOAD_FRAGS(SB, STEP) do {                                              \
    const uint32_t acx = (uint32_t)((STEP) * 2) + a_c;                         \
    const uint32_t bcx = (uint32_t)((STEP) * 2) + b_c;                         \
    _Pragma("unroll")                                                          \
    for (int mi_ = 0; mi_ < 2; ++mi_) {                                        \
        uint32_t ad = (SB) + aAddr[mi_] + ((acx ^ aSw[mi_]) << 4);             \
        ldsm4(Ah[mi_], ad);                                                    \
        ldsm4(Al[mi_], ad + (ALO_O - AHI_O));                                  \
    }                                                                          \
    _Pragma("unroll")                                                          \
    for (int ni_ = 0; ni_ < 4; ++ni_) {                                        \
        uint32_t bd = (SB) + bAddr[ni_] + ((bcx ^ bSw[ni_]) << 4);             \
        ldsm4(Bh[ni_], bd);                                                    \
    }                                                                          \
} while (0)

#define MMA_STEP() do {                                                        \
    _Pragma("unroll")                                                          \
    for (int mi_ = 0; mi_ < 2; ++mi_) {                                        \
        _Pragma("unroll")                                                      \
        for (int nj_ = 0; nj_ < 8; ++nj_) {                                    \
            const int ni_ = nj_ >> 1, h_ = (nj_ & 1) * 2;                      \
            mma16816(acc[mi_][nj_], Ah[mi_], Bh[ni_][h_], Bh[ni_][h_ + 1]);    \
            mma16816(acc[mi_][nj_], Al[mi_], Bh[ni_][h_], Bh[ni_][h_ + 1]);    \
        }                                                                      \
    }                                                                          \
} while (0)

template<int K_TOT, bool FUSE1>
__global__ __launch_bounds__(NTHR, 4)
void hmma_gemm(const __half* __restrict__ Ahi,
               const __half* __restrict__ Alo,
               const __half* __restrict__ Bmat,
               const float* __restrict__ bias,
               __half* __restrict__ OutHi,
               __half* __restrict__ OutLo,
               float* __restrict__ OutF,
               int Ncols)
{
    extern __shared__ char smem_raw[];
    const uint32_t sbase = smem_u32(smem_raw);

    const int tid = threadIdx.x;
    const int wid = tid >> 5;
    const int l   = tid & 31;
    const int m0  = blockIdx.y * GBM;
    const int n0  = blockIdx.x * GBN;
    const int wm  = wid & 1;        // 2 warp-rows of 32
    const int wn  = wid >> 1;       // 2 warp-cols of 64

    // ---- global->smem load plan: 8 x 16B units per thread -------------------
    // units: 0..1 Ahi (rows r0+{0,32}), 2..3 Alo, 4..7 B (rows r0+{0,32,64,96})
    const char* pm[3];
    {
        const int r0 = tid >> 2, cc = tid & 3;
        pm[0] = (const char*)(Ahi  + (size_t)(m0 + r0) * K_TOT) + cc * 16;
        pm[1] = (const char*)(Alo  + (size_t)(m0 + r0) * K_TOT) + cc * 16;
        pm[2] = (const char*)(Bmat + (size_t)(n0 + r0) * K_TOT) + cc * 16;
    }
    // per-thread base smem offset; swizzle chunk' = c ^ ((row>>1)&3)
    const uint32_t s0 = (uint32_t)((tid >> 2) * 64)
                      + ((uint32_t)((tid & 3) ^ ((tid >> 3) & 3)) << 4);

    // ---- ldmatrix address pieces -------------------------------------------
    uint32_t aAddr[2], aSw[2], bAddr[4], bSw[4];
    #pragma unroll
    for (int mi = 0; mi < 2; ++mi) {
        int row = wm * 32 + mi * 16 + ((l >> 3) & 1) * 8 + (l & 7);
        aAddr[mi] = AHI_O + (uint32_t)row * 64;
        aSw[mi]   = (uint32_t)((row >> 1) & 3);
    }
    #pragma unroll
    for (int ni = 0; ni < 4; ++ni) {
        int row = wn * 64 + ni * 16 + ((l >> 4) & 1) * 8 + (l & 7);
        bAddr[ni] = B_O + (uint32_t)row * 64;
        bSw[ni]   = (uint32_t)((row >> 1) & 3);
    }
    const uint32_t a_c = (uint32_t)(l >> 4);
    const uint32_t b_c = (uint32_t)((l >> 3) & 1);

    float acc[2][8][4];
    #pragma unroll
    for (int i = 0; i < 2; ++i)
        #pragma unroll
        for (int j = 0; j < 8; ++j)
            #pragma unroll
            for (int q = 0; q < 4; ++q) acc[i][j][q] = 0.f;

    uint32_t Ah[2][4], Al[2][4], Bh[4][4];

    constexpr int NC = K_TOT / GBK;

    // unit tables: mat index and row-block k for each of the 8 units
    // i:    0  1  2  3  4  5  6  7
    // mat:  0  0  1  1  2  2  2  2
    // kblk: 0  1  0  1  0  1  2  3
    // smem: matbase + kblk*2048 + s0

    // prologue: fill stages 0 and 1 (chunks 0, 1)
    #pragma unroll
    for (int s = 0; s < 2; ++s) {
        const uint32_t sb = sbase + (uint32_t)s * STG_B;
        #pragma unroll
        for (int i = 0; i < 8; ++i) {
            const int mat = (i < 2) ? 0 : (i < 4) ? 1 : 2;
            const int kb  = (i < 2) ? i : (i < 4) ? (i - 2) : (i - 4);
            const char* p = pm[mat] + (size_t)kb * 32 * K_TOT * 2 + (size_t)s * 64;
            const uint32_t mb = (mat == 0) ? AHI_O : (mat == 1) ? ALO_O : B_O;
            cpasync16(sb + mb + (uint32_t)kb * 2048 + s0, p);
        }
        cp_commit();
    }

    #pragma unroll 1
    for (int c = 0; c < NC; ++c) {
        cp_wait<1>();                // chunk c complete (issued 2 chunks ago)
        __syncthreads();

        // prefetch chunk c+2 into the slot vacated by chunk c-1
        const int pf = c + 2;
        if (pf < NC) {
            const uint32_t sbpf = sbase + (uint32_t)(pf % STAGES) * STG_B;
            #pragma unroll
            for (int i = 0; i < 8; ++i) {
                const int mat = (i < 2) ? 0 : (i < 4) ? 1 : 2;
                const int kb  = (i < 2) ? i : (i < 4) ? (i - 2) : (i - 4);
                const char* p = pm[mat] + (size_t)kb * 32 * K_TOT * 2 + (size_t)pf * 64;
                const uint32_t mb = (mat == 0) ? AHI_O : (mat == 1) ? ALO_O : B_O;
                cpasync16(sbpf + mb + (uint32_t)kb * 2048 + s0, p);
            }
        }
        cp_commit();

        const uint32_t sb = sbase + (uint32_t)(c % STAGES) * STG_B;
        #pragma unroll
        for (int step = 0; step < 2; ++step) {
            LOAD_FRAGS(sb, step);
            MMA_STEP();
        }
    }

    // ---- epilogue -----------------------------------------------------------
    const int r_base = m0 + wm * 32 + (l >> 2);
    const int c_base = n0 + wn * 64 + (l & 3) * 2;
    #pragma unroll
    for (int mi = 0; mi < 2; ++mi) {
        #pragma unroll
        for (int nj = 0; nj < 8; ++nj) {
            const int col = c_base + nj * 8;
            const float bb0 = __ldg(bias + col);
            const float bb1 = __ldg(bias + col + 1);
            #pragma unroll
            for (int hh = 0; hh < 2; ++hh) {
                const int row = r_base + mi * 16 + hh * 8;
                float t0 = acc[mi][nj][hh * 2 + 0] + bb0;
                float t1 = acc[mi][nj][hh * 2 + 1] + bb1;
                if (FUSE1) {
                    t0 = 0.5f * t0 * (1.0f + erff(t0 * 0.70710678118654752f));
                    t1 = 0.5f * t1 * (1.0f + erff(t1 * 0.70710678118654752f));
                    __half h0, l0, h1, l1;
                    split_one(t0, h0, l0); split_one(t1, h1, l1);
                    uint32_t ph = ((uint32_t)__half_as_ushort(h1) << 16) | __half_as_ushort(h0);
                    uint32_t pl = ((uint32_t)__half_as_ushort(l1) << 16) | __half_as_ushort(l0);
                    *reinterpret_cast<uint32_t*>(OutHi + (size_t)row * Ncols + col) = ph;
                    *reinterpret_cast<uint32_t*>(OutLo + (size_t)row * Ncols + col) = pl;
                } else {
                    float2 o; o.x = t0; o.y = t1;
                    *reinterpret_cast<float2*>(OutF + (size_t)row * Ncols + col) = o;
                }
            }
        }
    }
}

// ---------------- launcher ----------------------------------------------------
extern "C" void kernel_launch(void* const* d_in, const int* in_sizes, int n_in,
                              void* d_out, int out_size) {
    (void)in_sizes; (void)n_in; (void)out_size;
    const float* X  = (const float*)d_in[0];
    const float* W1 = (const float*)d_in[1];
    const float* b1 = (const float*)d_in[2];
    const float* W2 = (const float*)d_in[3];
    const float* b2 = (const float*)d_in[4];
    float* out = (float*)d_out;

    __half *Xhi, *Xlo, *W1T, *W2T, *Thi, *Tlo;
    cudaGetSymbolAddress((void**)&Xhi, g_Xhi);
    cudaGetSymbolAddress((void**)&Xlo, g_Xlo);
    cudaGetSymbolAddress((void**)&W1T, g_W1T);
    cudaGetSymbolAddress((void**)&W2T, g_W2T);
    cudaGetSymbolAddress((void**)&Thi, g_Thi);
    cudaGetSymbolAddress((void**)&Tlo, g_Tlo);

    cudaFuncSetAttribute(hmma_gemm<D_SZ, true>,
                         cudaFuncAttributeMaxDynamicSharedMemorySize, SMEM_REQ);
    cudaFuncSetAttribute(hmma_gemm<H_SZ, false>,
                         cudaFuncAttributeMaxDynamicSharedMemorySize, SMEM_REQ);

    // 1) split X into hi/lo fp16
    split_kernel<<<4096, 256>>>(X, Xhi, Xlo, M_TOT * D_SZ / 4);
    // 2) transpose weights into K-major single fp16
    transpose_half_kernel<<<dim3(H_SZ / 32, D_SZ / 32), dim3(32, 8)>>>(W1, W1T, D_SZ, H_SZ);
    transpose_half_kernel<<<dim3(D_SZ / 32, H_SZ / 32), dim3(32, 8)>>>(W2, W2T, H_SZ, D_SZ);
    // 3) GEMM1: T = GELU(X @ W1 + b1), split-fp16 output
    hmma_gemm<D_SZ, true><<<dim3(H_SZ / GBN, M_TOT / GBM), NTHR, SMEM_REQ>>>(
        Xhi, Xlo, W1T, b1, Thi, Tlo, nullptr, H_SZ);
    // 4) GEMM2: out = T @ W2 + b2, fp32 output
    hmma_gemm<H_SZ, false><<<dim3(D_SZ / GBN, M_TOT / GBM), NTHR, SMEM_REQ>>>(
        Thi, Tlo, W2T, b2, nullptr, nullptr, out, D_SZ);
    // 5) out[:,0,:] = X[:,0,:]
    copy_first_token_kernel<<<(B_SZ * D_SZ + 255) / 256, 256>>>(X, out);
}

// round 10
// speedup vs baseline: 3.3582x; 1.2484x over previous
#include <cuda_runtime.h>
#include <cuda_fp16.h>
#include <cstdint>
#include <math.h>

#define B_SZ 8
#define S_SZ 2048
#define D_SZ 1024
#define H_SZ 2048
#define M_TOT 16384

// ---------------- scratch (device globals) ------------------------------------
__device__ __half g_Xhi[(size_t)M_TOT * D_SZ];
__device__ __half g_Xlo[(size_t)M_TOT * D_SZ];
__device__ __half g_W1T[(size_t)H_SZ * D_SZ];    // [N=2048][K=1024] fp16
__device__ __half g_W2T[(size_t)D_SZ * H_SZ];    // [N=1024][K=2048] fp16
__device__ __half g_T[(size_t)M_TOT * H_SZ];     // GEMM1 out, single fp16

// ---------------- small PTX helpers (sm_80-level, compute_103-safe) ------------
static __device__ __forceinline__ uint32_t smem_u32(const void* p) {
    uint32_t a;
    asm("{ .reg .u64 t; cvta.to.shared.u64 t, %1; cvt.u32.u64 %0, t; }"
        : "=r"(a) : "l"(p));
    return a;
}
static __device__ __forceinline__ void cpasync16(uint32_t dst, const void* src) {
    asm volatile("cp.async.cg.shared.global [%0], [%1], 16;"
                 :: "r"(dst), "l"(src) : "memory");
}
static __device__ __forceinline__ void cp_commit() {
    asm volatile("cp.async.commit_group;" ::: "memory");
}
template<int N>
static __device__ __forceinline__ void cp_wait() {
    asm volatile("cp.async.wait_group %0;" :: "n"(N) : "memory");
}
static __device__ __forceinline__ void ldsm4(uint32_t* r, uint32_t addr) {
    asm volatile("ldmatrix.sync.aligned.m8n8.x4.shared.b16 {%0,%1,%2,%3}, [%4];"
                 : "=r"(r[0]), "=r"(r[1]), "=r"(r[2]), "=r"(r[3]) : "r"(addr));
}
static __device__ __forceinline__ void mma16816(float* d, const uint32_t* a,
                                                uint32_t b0, uint32_t b1) {
    asm volatile(
        "mma.sync.aligned.m16n8k16.row.col.f32.f16.f16.f32 "
        "{%0,%1,%2,%3}, {%4,%5,%6,%7}, {%8,%9}, {%0,%1,%2,%3};"
        : "+f"(d[0]), "+f"(d[1]), "+f"(d[2]), "+f"(d[3])
        : "r"(a[0]), "r"(a[1]), "r"(a[2]), "r"(a[3]), "r"(b0), "r"(b1));
}

// ---------------- prep kernels ------------------------------------------------
static __device__ __forceinline__ void split_one(float x, __half& h, __half& l) {
    h = __float2half_rn(x);
    l = __float2half_rn(x - __half2float(h));
}

__global__ void split_kernel(const float* __restrict__ X,
                             __half* __restrict__ Hi,
                             __half* __restrict__ Lo, int n4) {
    int stride = gridDim.x * blockDim.x;
    for (int i = blockIdx.x * blockDim.x + threadIdx.x; i < n4; i += stride) {
        float4 v = reinterpret_cast<const float4*>(X)[i];
        __half h0,h1,h2,h3,l0,l1,l2,l3;
        split_one(v.x,h0,l0); split_one(v.y,h1,l1);
        split_one(v.z,h2,l2); split_one(v.w,h3,l3);
        uint2 ph, pl;
        ph.x = ((uint32_t)__half_as_ushort(h1) << 16) | __half_as_ushort(h0);
        ph.y = ((uint32_t)__half_as_ushort(h3) << 16) | __half_as_ushort(h2);
        pl.x = ((uint32_t)__half_as_ushort(l1) << 16) | __half_as_ushort(l0);
        pl.y = ((uint32_t)__half_as_ushort(l3) << 16) | __half_as_ushort(l2);
        reinterpret_cast<uint2*>(Hi)[i] = ph;
        reinterpret_cast<uint2*>(Lo)[i] = pl;
    }
}

// W [R][C] fp32 -> WT [C][R] fp16
__global__ void transpose_half_kernel(const float* __restrict__ W,
                                      __half* __restrict__ T,
                                      int R, int C) {
    __shared__ float t[32][33];
    int c0 = blockIdx.x * 32, r0 = blockIdx.y * 32;
    int tx = threadIdx.x, ty = threadIdx.y;
    #pragma unroll
    for (int i = ty; i < 32; i += 8)
        t[i][tx] = W[(size_t)(r0 + i) * C + c0 + tx];
    __syncthreads();
    #pragma unroll
    for (int i = ty; i < 32; i += 8) {
        float x = t[tx][i];                 // = W[r0+tx][c0+i]
        T[(size_t)(c0 + i) * R + r0 + tx] = __float2half_rn(x);
    }
}

__global__ void copy_first_token_kernel(const float* __restrict__ X,
                                        float* __restrict__ out) {
    int i = blockIdx.x * blockDim.x + threadIdx.x;
    if (i >= B_SZ * D_SZ) return;
    int b = i >> 10, d = i & 1023;
    size_t off = ((size_t)b * S_SZ) * D_SZ + d;
    out[off] = X[off];
}

// ---------------- HMMA (mma.sync) fp16 GEMM ------------------------------------
// SPLIT_A=1: C = act((Ahi+Alo)·B^T + bias)  (2 products)
// SPLIT_A=0: C = act(A·B^T + bias)          (1 product)
// CTA tile 64x128x32, 3-stage cp.async, 4 warps of 32x64, 4 CTAs/SM.
#define GBM 64
#define GBN 128
#define GBK 32
#define NTHR 128
#define STAGES 3

template<int K_TOT, bool FUSE1, bool SPLIT_A>
__global__ __launch_bounds__(NTHR, 4)
void hmma_gemm(const __half* __restrict__ Ahi,
               const __half* __restrict__ Alo,
               const __half* __restrict__ Bmat,
               const float* __restrict__ bias,
               __half* __restrict__ OutT,
               float* __restrict__ OutF,
               int Ncols)
{
    // stage layout: Ahi 4K | (Alo 4K) | B 8K
    constexpr uint32_t ALO_O = 4096;
    constexpr uint32_t B_O   = SPLIT_A ? 8192 : 4096;
    constexpr uint32_t STG_B = SPLIT_A ? 16384 : 12288;
    constexpr int      NU    = SPLIT_A ? 8 : 6;

    extern __shared__ char smem_raw[];
    const uint32_t sbase = smem_u32(smem_raw);

    const int tid = threadIdx.x;
    const int wid = tid >> 5;
    const int l   = tid & 31;
    const int m0  = blockIdx.y * GBM;
    const int n0  = blockIdx.x * GBN;
    const int wm  = wid & 1;        // 2 warp-rows of 32
    const int wn  = wid >> 1;       // 2 warp-cols of 64

    // ---- global->smem load plan: NU x 16B units per thread ------------------
    const char* pm[3];
    {
        const int r0 = tid >> 2, cc = tid & 3;
        pm[0] = (const char*)(Ahi  + (size_t)(m0 + r0) * K_TOT) + cc * 16;
        pm[1] = SPLIT_A ? (const char*)(Alo + (size_t)(m0 + r0) * K_TOT) + cc * 16
                        : pm[0];
        pm[2] = (const char*)(Bmat + (size_t)(n0 + r0) * K_TOT) + cc * 16;
    }
    // per-thread base smem offset; swizzle chunk' = c ^ ((row>>1)&3)
    const uint32_t s0 = (uint32_t)((tid >> 2) * 64)
                      + ((uint32_t)((tid & 3) ^ ((tid >> 3) & 3)) << 4);

    // ---- ldmatrix address pieces -------------------------------------------
    uint32_t aAddr[2], aSw[2], bAddr[4], bSw[4];
    #pragma unroll
    for (int mi = 0; mi < 2; ++mi) {
        int row = wm * 32 + mi * 16 + ((l >> 3) & 1) * 8 + (l & 7);
        aAddr[mi] = (uint32_t)row * 64;
        aSw[mi]   = (uint32_t)((row >> 1) & 3);
    }
    #pragma unroll
    for (int ni = 0; ni < 4; ++ni) {
        int row = wn * 64 + ni * 16 + ((l >> 4) & 1) * 8 + (l & 7);
        bAddr[ni] = B_O + (uint32_t)row * 64;
        bSw[ni]   = (uint32_t)((row >> 1) & 3);
    }
    const uint32_t a_c = (uint32_t)(l >> 4);
    const uint32_t b_c = (uint32_t)((l >> 3) & 1);

    float acc[2][8][4];
    #pragma unroll
    for (int i = 0; i < 2; ++i)
        #pragma unroll
        for (int j = 0; j < 8; ++j)
            #pragma unroll
            for (int q = 0; q < 4; ++q) acc[i][j][q] = 0.f;

    uint32_t Ah[2][4], Al[2][4], Bh[4][4];

    constexpr int NC = K_TOT / GBK;

    // unit tables (SPLIT_A): i: 0..1 Ahi, 2..3 Alo, 4..7 B;  (!SPLIT_A): 0..1 A, 2..5 B
    auto unit_src = [&](int i, int chunk) -> const char* {
        int mat, kb;
        if (SPLIT_A) { mat = (i < 2) ? 0 : (i < 4) ? 1 : 2;
                       kb  = (i < 2) ? i : (i < 4) ? (i - 2) : (i - 4); }
        else         { mat = (i < 2) ? 0 : 2;
                       kb  = (i < 2) ? i : (i - 2); }
        return pm[mat] + (size_t)kb * 32 * K_TOT * 2 + (size_t)chunk * 64;
    };
    auto unit_dst = [&](int i, uint32_t sb) -> uint32_t {
        int mat, kb;
        if (SPLIT_A) { mat = (i < 2) ? 0 : (i < 4) ? 1 : 2;
                       kb  = (i < 2) ? i : (i < 4) ? (i - 2) : (i - 4); }
        else         { mat = (i < 2) ? 0 : 2;
                       kb  = (i < 2) ? i : (i - 2); }
        const uint32_t mb = (mat == 0) ? 0u : (mat == 1) ? ALO_O : B_O;
        return sb + mb + (uint32_t)kb * 2048 + s0;
    };

    // prologue: fill stages 0 and 1 (chunks 0, 1)
    #pragma unroll
    for (int s = 0; s < 2; ++s) {
        const uint32_t sb = sbase + (uint32_t)s * STG_B;
        #pragma unroll
        for (int i = 0; i < NU; ++i)
            cpasync16(unit_dst(i, sb), unit_src(i, s));
        cp_commit();
    }

    #pragma unroll 1
    for (int c = 0; c < NC; ++c) {
        cp_wait<1>();                // chunk c complete (issued 2 chunks ago)
        __syncthreads();

        // prefetch chunk c+2 into the slot vacated by chunk c-1
        const int pf = c + 2;
        if (pf < NC) {
            const uint32_t sbpf = sbase + (uint32_t)(pf % STAGES) * STG_B;
            #pragma unroll
            for (int i = 0; i < NU; ++i)
                cpasync16(unit_dst(i, sbpf), unit_src(i, pf));
        }
        cp_commit();

        const uint32_t sb = sbase + (uint32_t)(c % STAGES) * STG_B;
        #pragma unroll
        for (int step = 0; step < 2; ++step) {
            const uint32_t acx = (uint32_t)(step * 2) + a_c;
            const uint32_t bcx = (uint32_t)(step * 2) + b_c;
            #pragma unroll
            for (int mi = 0; mi < 2; ++mi) {
                uint32_t ad = sb + aAddr[mi] + ((acx ^ aSw[mi]) << 4);
                ldsm4(Ah[mi], ad);
                if (SPLIT_A) ldsm4(Al[mi], ad + ALO_O);
            }
            #pragma unroll
            for (int ni = 0; ni < 4; ++ni) {
                uint32_t bd = sb + bAddr[ni] + ((bcx ^ bSw[ni]) << 4);
                ldsm4(Bh[ni], bd);
            }
            #pragma unroll
            for (int mi = 0; mi < 2; ++mi) {
                #pragma unroll
                for (int nj = 0; nj < 8; ++nj) {
                    const int ni = nj >> 1, h = (nj & 1) * 2;
                    mma16816(acc[mi][nj], Ah[mi], Bh[ni][h], Bh[ni][h + 1]);
                    if (SPLIT_A)
                        mma16816(acc[mi][nj], Al[mi], Bh[ni][h], Bh[ni][h + 1]);
                }
            }
        }
    }

    // ---- epilogue -----------------------------------------------------------
    const int r_base = m0 + wm * 32 + (l >> 2);
    const int c_base = n0 + wn * 64 + (l & 3) * 2;
    #pragma unroll
    for (int mi = 0; mi < 2; ++mi) {
        #pragma unroll
        for (int nj = 0; nj < 8; ++nj) {
            const int col = c_base + nj * 8;
            const float bb0 = __ldg(bias + col);
            const float bb1 = __ldg(bias + col + 1);
            #pragma unroll
            for (int hh = 0; hh < 2; ++hh) {
                const int row = r_base + mi * 16 + hh * 8;
                float t0 = acc[mi][nj][hh * 2 + 0] + bb0;
                float t1 = acc[mi][nj][hh * 2 + 1] + bb1;
                if (FUSE1) {
                    t0 = 0.5f * t0 * (1.0f + erff(t0 * 0.70710678118654752f));
                    t1 = 0.5f * t1 * (1.0f + erff(t1 * 0.70710678118654752f));
                    __half h0 = __float2half_rn(t0);
                    __half h1 = __float2half_rn(t1);
                    uint32_t ph = ((uint32_t)__half_as_ushort(h1) << 16) | __half_as_ushort(h0);
                    *reinterpret_cast<uint32_t*>(OutT + (size_t)row * Ncols + col) = ph;
                } else {
                    float2 o; o.x = t0; o.y = t1;
                    *reinterpret_cast<float2*>(OutF + (size_t)row * Ncols + col) = o;
                }
            }
        }
    }
}

// ---------------- launcher ----------------------------------------------------
extern "C" void kernel_launch(void* const* d_in, const int* in_sizes, int n_in,
                              void* d_out, int out_size) {
    (void)in_sizes; (void)n_in; (void)out_size;
    const float* X  = (const float*)d_in[0];
    const float* W1 = (const float*)d_in[1];
    const float* b1 = (const float*)d_in[2];
    const float* W2 = (const float*)d_in[3];
    const float* b2 = (const float*)d_in[4];
    float* out = (float*)d_out;

    __half *Xhi, *Xlo, *W1T, *W2T, *T;
    cudaGetSymbolAddress((void**)&Xhi, g_Xhi);
    cudaGetSymbolAddress((void**)&Xlo, g_Xlo);
    cudaGetSymbolAddress((void**)&W1T, g_W1T);
    cudaGetSymbolAddress((void**)&W2T, g_W2T);
    cudaGetSymbolAddress((void**)&T,   g_T);

    cudaFuncSetAttribute(hmma_gemm<D_SZ, true, true>,
                         cudaFuncAttributeMaxDynamicSharedMemorySize, 3 * 16384);
    cudaFuncSetAttribute(hmma_gemm<H_SZ, false, false>,
                         cudaFuncAttributeMaxDynamicSharedMemorySize, 3 * 12288);

    // 1) split X into hi/lo fp16
    split_kernel<<<4096, 256>>>(X, Xhi, Xlo, M_TOT * D_SZ / 4);
    // 2) transpose weights into K-major single fp16
    transpose_half_kernel<<<dim3(H_SZ / 32, D_SZ / 32), dim3(32, 8)>>>(W1, W1T, D_SZ, H_SZ);
    transpose_half_kernel<<<dim3(D_SZ / 32, H_SZ / 32), dim3(32, 8)>>>(W2, W2T, H_SZ, D_SZ);
    // 3) GEMM1: T = GELU(X @ W1 + b1), single-fp16 output (split A)
    hmma_gemm<D_SZ, true, true><<<dim3(H_SZ / GBN, M_TOT / GBM), NTHR, 3 * 16384>>>(
        Xhi, Xlo, W1T, b1, T, nullptr, H_SZ);
    // 4) GEMM2: out = T @ W2 + b2, fp32 output (single A)
    hmma_gemm<H_SZ, false, false><<<dim3(D_SZ / GBN, M_TOT / GBM), NTHR, 3 * 12288>>>(
        T, nullptr, W2T, b2, nullptr, out, D_SZ);
    // 5) out[:,0,:] = X[:,0,:]
    copy_first_token_kernel<<<(B_SZ * D_SZ + 255) / 256, 256>>>(X, out);
}

// round 11
// speedup vs baseline: 4.2766x; 1.2735x over previous
#include <cuda_runtime.h>
#include <cuda_fp16.h>
#include <cstdint>
#include <math.h>

#define B_SZ 8
#define S_SZ 2048
#define D_SZ 1024
#define H_SZ 2048
#define M_TOT 16384

// ---------------- scratch (device globals) ------------------------------------
__device__ __half g_Xh[(size_t)M_TOT * D_SZ];    // X as fp16
__device__ __half g_W1T[(size_t)H_SZ * D_SZ];    // [N=2048][K=1024] fp16
__device__ __half g_W2T[(size_t)D_SZ * H_SZ];    // [N=1024][K=2048] fp16
__device__ __half g_T[(size_t)M_TOT * H_SZ];     // GEMM1 out, fp16

// ---------------- small PTX helpers (sm_80-level, compute_103-safe) ------------
static __device__ __forceinline__ uint32_t smem_u32(const void* p) {
    uint32_t a;
    asm("{ .reg .u64 t; cvta.to.shared.u64 t, %1; cvt.u32.u64 %0, t; }"
        : "=r"(a) : "l"(p));
    return a;
}
static __device__ __forceinline__ void cpasync16(uint32_t dst, const void* src) {
    asm volatile("cp.async.cg.shared.global [%0], [%1], 16;"
                 :: "r"(dst), "l"(src) : "memory");
}
static __device__ __forceinline__ void cp_commit() {
    asm volatile("cp.async.commit_group;" ::: "memory");
}
template<int N>
static __device__ __forceinline__ void cp_wait() {
    asm volatile("cp.async.wait_group %0;" :: "n"(N) : "memory");
}
static __device__ __forceinline__ void ldsm4(uint32_t* r, uint32_t addr) {
    asm volatile("ldmatrix.sync.aligned.m8n8.x4.shared.b16 {%0,%1,%2,%3}, [%4];"
                 : "=r"(r[0]), "=r"(r[1]), "=r"(r[2]), "=r"(r[3]) : "r"(addr));
}
static __device__ __forceinline__ void mma16816(float* d, const uint32_t* a,
                                                uint32_t b0, uint32_t b1) {
    asm volatile(
        "mma.sync.aligned.m16n8k16.row.col.f32.f16.f16.f32 "
        "{%0,%1,%2,%3}, {%4,%5,%6,%7}, {%8,%9}, {%0,%1,%2,%3};"
        : "+f"(d[0]), "+f"(d[1]), "+f"(d[2]), "+f"(d[3])
        : "r"(a[0]), "r"(a[1]), "r"(a[2]), "r"(a[3]), "r"(b0), "r"(b1));
}

// ---------------- prep kernels ------------------------------------------------
__global__ void convert_half_kernel(const float* __restrict__ X,
                                    __half* __restrict__ H, int n4) {
    int stride = gridDim.x * blockDim.x;
    for (int i = blockIdx.x * blockDim.x + threadIdx.x; i < n4; i += stride) {
        float4 v = reinterpret_cast<const float4*>(X)[i];
        uint2 p;
        p.x = ((uint32_t)__half_as_ushort(__float2half_rn(v.y)) << 16)
            | __half_as_ushort(__float2half_rn(v.x));
        p.y = ((uint32_t)__half_as_ushort(__float2half_rn(v.w)) << 16)
            | __half_as_ushort(__float2half_rn(v.z));
        reinterpret_cast<uint2*>(H)[i] = p;
    }
}

// W [R][C] fp32 -> WT [C][R] fp16
__global__ void transpose_half_kernel(const float* __restrict__ W,
                                      __half* __restrict__ T,
                                      int R, int C) {
    __shared__ float t[32][33];
    int c0 = blockIdx.x * 32, r0 = blockIdx.y * 32;
    int tx = threadIdx.x, ty = threadIdx.y;
    #pragma unroll
    for (int i = ty; i < 32; i += 8)
        t[i][tx] = W[(size_t)(r0 + i) * C + c0 + tx];
    __syncthreads();
    #pragma unroll
    for (int i = ty; i < 32; i += 8) {
        float x = t[tx][i];                 // = W[r0+tx][c0+i]
        T[(size_t)(c0 + i) * R + r0 + tx] = __float2half_rn(x);
    }
}

__global__ void copy_first_token_kernel(const float* __restrict__ X,
                                        float* __restrict__ out) {
    int i = blockIdx.x * blockDim.x + threadIdx.x;
    if (i >= B_SZ * D_SZ) return;
    int b = i >> 10, d = i & 1023;
    size_t off = ((size_t)b * S_SZ) * D_SZ + d;
    out[off] = X[off];
}

// ---------------- HMMA (mma.sync) fp16 GEMM ------------------------------------
// C[M,N] = act(A·B^T + bias); A, B fp16 K-major; fp32 accum.
// CTA tile 64x128x32, 3-stage cp.async (36KB), 4 warps of 32x64, 4 CTAs/SM.
#define GBM 64
#define GBN 128
#define GBK 32
#define NTHR 128
#define STAGES 3
#define STG_B 12288                 // A 4K | B 8K
#define B_O   4096

template<int K_TOT, bool FUSE1>
__global__ __launch_bounds__(NTHR, 4)
void hmma_gemm(const __half* __restrict__ Amat,
               const __half* __restrict__ Bmat,
               const float* __restrict__ bias,
               __half* __restrict__ OutT,
               float* __restrict__ OutF,
               int Ncols)
{
    extern __shared__ char smem_raw[];
    const uint32_t sbase = smem_u32(smem_raw);

    const int tid = threadIdx.x;
    const int wid = tid >> 5;
    const int l   = tid & 31;
    const int m0  = blockIdx.y * GBM;
    const int n0  = blockIdx.x * GBN;
    const int wm  = wid & 1;        // 2 warp-rows of 32
    const int wn  = wid >> 1;       // 2 warp-cols of 64

    // ---- global->smem load plan: 6 x 16B units per thread -------------------
    // units 0..1: A rows r0+{0,32}; units 2..5: B rows r0+{0,32,64,96}
    const char* pmA;
    const char* pmB;
    {
        const int r0 = tid >> 2, cc = tid & 3;
        pmA = (const char*)(Amat + (size_t)(m0 + r0) * K_TOT) + cc * 16;
        pmB = (const char*)(Bmat + (size_t)(n0 + r0) * K_TOT) + cc * 16;
    }
    // per-thread base smem offset; swizzle chunk' = c ^ ((row>>1)&3)
    const uint32_t s0 = (uint32_t)((tid >> 2) * 64)
                      + ((uint32_t)((tid & 3) ^ ((tid >> 3) & 3)) << 4);

    // ---- ldmatrix address pieces -------------------------------------------
    uint32_t aAddr[2], aSw[2], bAddr[4], bSw[4];
    #pragma unroll
    for (int mi = 0; mi < 2; ++mi) {
        int row = wm * 32 + mi * 16 + ((l >> 3) & 1) * 8 + (l & 7);
        aAddr[mi] = (uint32_t)row * 64;
        aSw[mi]   = (uint32_t)((row >> 1) & 3);
    }
    #pragma unroll
    for (int ni = 0; ni < 4; ++ni) {
        int row = wn * 64 + ni * 16 + ((l >> 4) & 1) * 8 + (l & 7);
        bAddr[ni] = B_O + (uint32_t)row * 64;
        bSw[ni]   = (uint32_t)((row >> 1) & 3);
    }
    const uint32_t a_c = (uint32_t)(l >> 4);
    const uint32_t b_c = (uint32_t)((l >> 3) & 1);

    float acc[2][8][4];
    #pragma unroll
    for (int i = 0; i < 2; ++i)
        #pragma unroll
        for (int j = 0; j < 8; ++j)
            #pragma unroll
            for (int q = 0; q < 4; ++q) acc[i][j][q] = 0.f;

    uint32_t Ah[2][4], Bh[4][4];

    constexpr int NC = K_TOT / GBK;

    // unit i: 0..1 -> A kblk i; 2..5 -> B kblk i-2
    auto unit_src = [&](int i, int chunk) -> const char* {
        const char* base = (i < 2) ? pmA : pmB;
        const int kb = (i < 2) ? i : (i - 2);
        return base + (size_t)kb * 32 * K_TOT * 2 + (size_t)chunk * 64;
    };
    auto unit_dst = [&](int i, uint32_t sb) -> uint32_t {
        const int kb = (i < 2) ? i : (i - 2);
        const uint32_t mb = (i < 2) ? 0u : B_O;
        return sb + mb + (uint32_t)kb * 2048 + s0;
    };

    // prologue: fill stages 0 and 1 (chunks 0, 1)
    #pragma unroll
    for (int s = 0; s < 2; ++s) {
        const uint32_t sb = sbase + (uint32_t)s * STG_B;
        #pragma unroll
        for (int i = 0; i < 6; ++i)
            cpasync16(unit_dst(i, sb), unit_src(i, s));
        cp_commit();
    }

    #pragma unroll 1
    for (int c = 0; c < NC; ++c) {
        cp_wait<1>();                // chunk c complete (issued 2 chunks ago)
        __syncthreads();

        // prefetch chunk c+2 into the slot vacated by chunk c-1
        const int pf = c + 2;
        if (pf < NC) {
            const uint32_t sbpf = sbase + (uint32_t)(pf % STAGES) * STG_B;
            #pragma unroll
            for (int i = 0; i < 6; ++i)
                cpasync16(unit_dst(i, sbpf), unit_src(i, pf));
        }
        cp_commit();

        const uint32_t sb = sbase + (uint32_t)(c % STAGES) * STG_B;
        #pragma unroll
        for (int step = 0; step < 2; ++step) {
            const uint32_t acx = (uint32_t)(step * 2) + a_c;
            const uint32_t bcx = (uint32_t)(step * 2) + b_c;
            #pragma unroll
            for (int mi = 0; mi < 2; ++mi)
                ldsm4(Ah[mi], sb + aAddr[mi] + ((acx ^ aSw[mi]) << 4));
            #pragma unroll
            for (int ni = 0; ni < 4; ++ni)
                ldsm4(Bh[ni], sb + bAddr[ni] + ((bcx ^ bSw[ni]) << 4));
            #pragma unroll
            for (int mi = 0; mi < 2; ++mi) {
                #pragma unroll
                for (int nj = 0; nj < 8; ++nj) {
                    const int ni = nj >> 1, h = (nj & 1) * 2;
                    mma16816(acc[mi][nj], Ah[mi], Bh[ni][h], Bh[ni][h + 1]);
                }
            }
        }
    }

    // ---- epilogue -----------------------------------------------------------
    const int r_base = m0 + wm * 32 + (l >> 2);
    const int c_base = n0 + wn * 64 + (l & 3) * 2;
    #pragma unroll
    for (int mi = 0; mi < 2; ++mi) {
        #pragma unroll
        for (int nj = 0; nj < 8; ++nj) {
            const int col = c_base + nj * 8;
            const float bb0 = __ldg(bias + col);
            const float bb1 = __ldg(bias + col + 1);
            #pragma unroll
            for (int hh = 0; hh < 2; ++hh) {
                const int row = r_base + mi * 16 + hh * 8;
                float t0 = acc[mi][nj][hh * 2 + 0] + bb0;
                float t1 = acc[mi][nj][hh * 2 + 1] + bb1;
                if (FUSE1) {
                    t0 = 0.5f * t0 * (1.0f + erff(t0 * 0.70710678118654752f));
                    t1 = 0.5f * t1 * (1.0f + erff(t1 * 0.70710678118654752f));
                    __half h0 = __float2half_rn(t0);
                    __half h1 = __float2half_rn(t1);
                    uint32_t ph = ((uint32_t)__half_as_ushort(h1) << 16) | __half_as_ushort(h0);
                    *reinterpret_cast<uint32_t*>(OutT + (size_t)row * Ncols + col) = ph;
                } else {
                    float2 o; o.x = t0; o.y = t1;
                    *reinterpret_cast<float2*>(OutF + (size_t)row * Ncols + col) = o;
                }
            }
        }
    }
}

// ---------------- launcher ----------------------------------------------------
extern "C" void kernel_launch(void* const* d_in, const int* in_sizes, int n_in,
                              void* d_out, int out_size) {
    (void)in_sizes; (void)n_in; (void)out_size;
    const float* X  = (const float*)d_in[0];
    const float* W1 = (const float*)d_in[1];
    const float* b1 = (const float*)d_in[2];
    const float* W2 = (const float*)d_in[3];
    const float* b2 = (const float*)d_in[4];
    float* out = (float*)d_out;

    __half *Xh, *W1T, *W2T, *T;
    cudaGetSymbolAddress((void**)&Xh,  g_Xh);
    cudaGetSymbolAddress((void**)&W1T, g_W1T);
    cudaGetSymbolAddress((void**)&W2T, g_W2T);
    cudaGetSymbolAddress((void**)&T,   g_T);

    cudaFuncSetAttribute(hmma_gemm<D_SZ, true>,
                         cudaFuncAttributeMaxDynamicSharedMemorySize, STAGES * STG_B);
    cudaFuncSetAttribute(hmma_gemm<H_SZ, false>,
                         cudaFuncAttributeMaxDynamicSharedMemorySize, STAGES * STG_B);

    // 1) convert X to fp16
    convert_half_kernel<<<4096, 256>>>(X, Xh, M_TOT * D_SZ / 4);
    // 2) transpose weights into K-major fp16
    transpose_half_kernel<<<dim3(H_SZ / 32, D_SZ / 32), dim3(32, 8)>>>(W1, W1T, D_SZ, H_SZ);
    transpose_half_kernel<<<dim3(D_SZ / 32, H_SZ / 32), dim3(32, 8)>>>(W2, W2T, H_SZ, D_SZ);
    // 3) GEMM1: T = GELU(X @ W1 + b1), fp16 output
    hmma_gemm<D_SZ, true><<<dim3(H_SZ / GBN, M_TOT / GBM), NTHR, STAGES * STG_B>>>(
        Xh, W1T, b1, T, nullptr, H_SZ);
    // 4) GEMM2: out = T @ W2 + b2, fp32 output
    hmma_gemm<H_SZ, false><<<dim3(D_SZ / GBN, M_TOT / GBM), NTHR, STAGES * STG_B>>>(
        T, W2T, b2, nullptr, out, D_SZ);
    // 5) out[:,0,:] = X[:,0,:]
    copy_first_token_kernel<<<(B_SZ * D_SZ + 255) / 256, 256>>>(X, out);
}

// round 13
// speedup vs baseline: 4.6578x; 1.0891x over previous
#include <cuda_runtime.h>
#include <cuda_fp16.h>
#include <cstdint>
#include <math.h>

#define B_SZ 8
#define S_SZ 2048
#define D_SZ 1024
#define H_SZ 2048
#define M_TOT 16384

// ---------------- scratch (device globals) ------------------------------------
__device__ __half g_Xh[(size_t)M_TOT * D_SZ];    // X as fp16
__device__ __half g_W1T[(size_t)H_SZ * D_SZ];    // [N=2048][K=1024] fp16
__device__ __half g_W2T[(size_t)D_SZ * H_SZ];    // [N=1024][K=2048] fp16
__device__ __half g_T[(size_t)M_TOT * H_SZ];     // GEMM1 out, fp16

// ---------------- small PTX helpers (sm_80-level, compute_103-safe) ------------
static __device__ __forceinline__ uint32_t smem_u32(const void* p) {
    uint32_t a;
    asm("{ .reg .u64 t; cvta.to.shared.u64 t, %1; cvt.u32.u64 %0, t; }"
        : "=r"(a) : "l"(p));
    return a;
}
static __device__ __forceinline__ void cpasync16(uint32_t dst, const void* src) {
    asm volatile("cp.async.cg.shared.global [%0], [%1], 16;"
                 :: "r"(dst), "l"(src) : "memory");
}
static __device__ __forceinline__ void cp_commit() {
    asm volatile("cp.async.commit_group;" ::: "memory");
}
template<int N>
static __device__ __forceinline__ void cp_wait() {
    asm volatile("cp.async.wait_group %0;" :: "n"(N) : "memory");
}
static __device__ __forceinline__ void ldsm4(uint32_t* r, uint32_t addr) {
    asm volatile("ldmatrix.sync.aligned.m8n8.x4.shared.b16 {%0,%1,%2,%3}, [%4];"
                 : "=r"(r[0]), "=r"(r[1]), "=r"(r[2]), "=r"(r[3]) : "r"(addr));
}
static __device__ __forceinline__ void mma16816(float* d, const uint32_t* a,
                                                uint32_t b0, uint32_t b1) {
    asm volatile(
        "mma.sync.aligned.m16n8k16.row.col.f32.f16.f16.f32 "
        "{%0,%1,%2,%3}, {%4,%5,%6,%7}, {%8,%9}, {%0,%1,%2,%3};"
        : "+f"(d[0]), "+f"(d[1]), "+f"(d[2]), "+f"(d[3])
        : "r"(a[0]), "r"(a[1]), "r"(a[2]), "r"(a[3]), "r"(b0), "r"(b1));
}

// ---------------- prep kernels ------------------------------------------------
__global__ void convert_half_kernel(const float* __restrict__ X,
                                    __half* __restrict__ H, int n4) {
    int stride = gridDim.x * blockDim.x;
    for (int i = blockIdx.x * blockDim.x + threadIdx.x; i < n4; i += stride) {
        float4 v = reinterpret_cast<const float4*>(X)[i];
        uint2 p;
        p.x = ((uint32_t)__half_as_ushort(__float2half_rn(v.y)) << 16)
            | __half_as_ushort(__float2half_rn(v.x));
        p.y = ((uint32_t)__half_as_ushort(__float2half_rn(v.w)) << 16)
            | __half_as_ushort(__float2half_rn(v.z));
        reinterpret_cast<uint2*>(H)[i] = p;
    }
}

// W [R][C] fp32 -> WT [C][R] fp16
__global__ void transpose_half_kernel(const float* __restrict__ W,
                                      __half* __restrict__ T,
                                      int R, int C) {
    __shared__ float t[32][33];
    int c0 = blockIdx.x * 32, r0 = blockIdx.y * 32;
    int tx = threadIdx.x, ty = threadIdx.y;
    #pragma unroll
    for (int i = ty; i < 32; i += 8)
        t[i][tx] = W[(size_t)(r0 + i) * C + c0 + tx];
    __syncthreads();
    #pragma unroll
    for (int i = ty; i < 32; i += 8) {
        float x = t[tx][i];                 // = W[r0+tx][c0+i]
        T[(size_t)(c0 + i) * R + r0 + tx] = __float2half_rn(x);
    }
}

__global__ void copy_first_token_kernel(const float* __restrict__ X,
                                        float* __restrict__ out) {
    int i = blockIdx.x * blockDim.x + threadIdx.x;
    if (i >= B_SZ * D_SZ) return;
    int b = i >> 10, d = i & 1023;
    size_t off = ((size_t)b * S_SZ) * D_SZ + d;
    out[off] = X[off];
}

// ---------------- HMMA (mma.sync) fp16 GEMM ------------------------------------
// C[M,N] = act(A·B^T + bias); A, B fp16 K-major; fp32 accum.
// CTA tile 64x128x64, 3-stage cp.async (72KB), 4 warps of 32x64, 3 CTAs/SM.
#define GBM 64
#define GBN 128
#define GBK 64
#define NTHR 128
#define STAGES 3
#define STG_B 24576                 // A 8K | B 16K
#define B_O   8192
#define SMEM_REQ (STAGES * STG_B)   // 72KB

template<int K_TOT, bool FUSE1>
__global__ __launch_bounds__(NTHR, 3)
void hmma_gemm(const __half* __restrict__ Amat,
               const __half* __restrict__ Bmat,
               const float* __restrict__ bias,
               __half* __restrict__ OutT,
               float* __restrict__ OutF,
               int Ncols)
{
    extern __shared__ char smem_raw[];
    const uint32_t sbase = smem_u32(smem_raw);

    const int tid = threadIdx.x;
    const int wid = tid >> 5;
    const int l   = tid & 31;
    const int m0  = blockIdx.y * GBM;
    const int n0  = blockIdx.x * GBN;
    const int wm  = wid & 1;        // 2 warp-rows of 32
    const int wn  = wid >> 1;       // 2 warp-cols of 64

    // ---- global->smem load plan: 12 x 16B units per thread ------------------
    // rows are 128B (64 fp16). thread: r0 = tid>>3 (0..15), cc = tid&7.
    // A units j=0..3: rows r0 + 16j ; B units j=0..7: rows r0 + 16j
    const char* pmA;
    const char* pmB;
    {
        const int r0 = tid >> 3, cc = tid & 7;
        pmA = (const char*)(Amat + (size_t)(m0 + r0) * K_TOT) + cc * 16;
        pmB = (const char*)(Bmat + (size_t)(n0 + r0) * K_TOT) + cc * 16;
    }
    // swizzle: chunk' = cc ^ (row & 7); (row+16j)&7 == r0&7, so s0 is constant
    const uint32_t s0 = (uint32_t)((tid >> 3) * 128)
                      + ((uint32_t)((tid & 7) ^ ((tid >> 3) & 7)) << 4);

    // ---- ldmatrix address pieces -------------------------------------------
    uint32_t aAddr[2], aSw[2], bAddr[4], bSw[4];
    #pragma unroll
    for (int mi = 0; mi < 2; ++mi) {
        int row = wm * 32 + mi * 16 + ((l >> 3) & 1) * 8 + (l & 7);
        aAddr[mi] = (uint32_t)row * 128;
        aSw[mi]   = (uint32_t)(row & 7);
    }
    #pragma unroll
    for (int ni = 0; ni < 4; ++ni) {
        int row = wn * 64 + ni * 16 + ((l >> 4) & 1) * 8 + (l & 7);
        bAddr[ni] = B_O + (uint32_t)row * 128;
        bSw[ni]   = (uint32_t)(row & 7);
    }
    const uint32_t a_c = (uint32_t)(l >> 4);
    const uint32_t b_c = (uint32_t)((l >> 3) & 1);

    float acc[2][8][4];
    #pragma unroll
    for (int i = 0; i < 2; ++i)
        #pragma unroll
        for (int j = 0; j < 8; ++j)
            #pragma unroll
            for (int q = 0; q < 4; ++q) acc[i][j][q] = 0.f;

    uint32_t Ah[2][4], Bh[4][4];

    constexpr int NC = K_TOT / GBK;

    // unit i: 0..3 -> A row-block i; 4..11 -> B row-block i-4
    auto unit_src = [&](int i, int chunk) -> const char* {
        const char* base = (i < 4) ? pmA : pmB;
        const int kb = (i < 4) ? i : (i - 4);
        return base + (size_t)kb * 16 * K_TOT * 2 + (size_t)chunk * 128;
    };
    auto unit_dst = [&](int i, uint32_t sb) -> uint32_t {
        const int kb = (i < 4) ? i : (i - 4);
        const uint32_t mb = (i < 4) ? 0u : B_O;
        return sb + mb + (uint32_t)kb * 2048 + s0;
    };

    // prologue: fill stages 0 and 1 (chunks 0, 1)
    #pragma unroll
    for (int s = 0; s < 2; ++s) {
        const uint32_t sb = sbase + (uint32_t)s * STG_B;
        #pragma unroll
        for (int i = 0; i < 12; ++i)
            cpasync16(unit_dst(i, sb), unit_src(i, s));
        cp_commit();
    }

    #pragma unroll 1
    for (int c = 0; c < NC; ++c) {
        cp_wait<1>();                // chunk c complete (issued 2 chunks ago)
        __syncthreads();

        // prefetch chunk c+2 into the slot vacated by chunk c-1
        const int pf = c + 2;
        if (pf < NC) {
            const uint32_t sbpf = sbase + (uint32_t)(pf % STAGES) * STG_B;
            #pragma unroll
            for (int i = 0; i < 12; ++i)
                cpasync16(unit_dst(i, sbpf), unit_src(i, pf));
        }
        cp_commit();

        const uint32_t sb = sbase + (uint32_t)(c % STAGES) * STG_B;
        #pragma unroll
        for (int step = 0; step < 4; ++step) {
            const uint32_t acx = (uint32_t)(step * 2) + a_c;
            const uint32_t bcx = (uint32_t)(step * 2) + b_c;
            #pragma unroll
            for (int mi = 0; mi < 2; ++mi)
                ldsm4(Ah[mi], sb + aAddr[mi] + ((acx ^ aSw[mi]) << 4));
            #pragma unroll
            for (int ni = 0; ni < 4; ++ni)
                ldsm4(Bh[ni], sb + bAddr[ni] + ((bcx ^ bSw[ni]) << 4));
            #pragma unroll
            for (int mi = 0; mi < 2; ++mi) {
                #pragma unroll
                for (int nj = 0; nj < 8; ++nj) {
                    const int ni = nj >> 1, h = (nj & 1) * 2;
                    mma16816(acc[mi][nj], Ah[mi], Bh[ni][h], Bh[ni][h + 1]);
                }
            }
        }
    }

    // ---- epilogue -----------------------------------------------------------
    const int r_base = m0 + wm * 32 + (l >> 2);
    const int c_base = n0 + wn * 64 + (l & 3) * 2;
    #pragma unroll
    for (int mi = 0; mi < 2; ++mi) {
        #pragma unroll
        for (int nj = 0; nj < 8; ++nj) {
            const int col = c_base + nj * 8;
            const float bb0 = __ldg(bias + col);
            const float bb1 = __ldg(bias + col + 1);
            #pragma unroll
            for (int hh = 0; hh < 2; ++hh) {
                const int row = r_base + mi * 16 + hh * 8;
                float t0 = acc[mi][nj][hh * 2 + 0] + bb0;
                float t1 = acc[mi][nj][hh * 2 + 1] + bb1;
                if (FUSE1) {
                    t0 = 0.5f * t0 * (1.0f + erff(t0 * 0.70710678118654752f));
                    t1 = 0.5f * t1 * (1.0f + erff(t1 * 0.70710678118654752f));
                    __half h0 = __float2half_rn(t0);
                    __half h1 = __float2half_rn(t1);
                    uint32_t ph = ((uint32_t)__half_as_ushort(h1) << 16) | __half_as_ushort(h0);
                    *reinterpret_cast<uint32_t*>(OutT + (size_t)row * Ncols + col) = ph;
                } else {
                    float2 o; o.x = t0; o.y = t1;
                    *reinterpret_cast<float2*>(OutF + (size_t)row * Ncols + col) = o;
                }
            }
        }
    }
}

// ---------------- launcher ----------------------------------------------------
extern "C" void kernel_launch(void* const* d_in, const int* in_sizes, int n_in,
                              void* d_out, int out_size) {
    (void)in_sizes; (void)n_in; (void)out_size;
    const float* X  = (const float*)d_in[0];
    const float* W1 = (const float*)d_in[1];
    const float* b1 = (const float*)d_in[2];
    const float* W2 = (const float*)d_in[3];
    const float* b2 = (const float*)d_in[4];
    float* out = (float*)d_out;

    __half *Xh, *W1T, *W2T, *T;
    cudaGetSymbolAddress((void**)&Xh,  g_Xh);
    cudaGetSymbolAddress((void**)&W1T, g_W1T);
    cudaGetSymbolAddress((void**)&W2T, g_W2T);
    cudaGetSymbolAddress((void**)&T,   g_T);

    cudaFuncSetAttribute(hmma_gemm<D_SZ, true>,
                         cudaFuncAttributeMaxDynamicSharedMemorySize, SMEM_REQ);
    cudaFuncSetAttribute(hmma_gemm<H_SZ, false>,
                         cudaFuncAttributeMaxDynamicSharedMemorySize, SMEM_REQ);

    // 1) convert X to fp16
    convert_half_kernel<<<4096, 256>>>(X, Xh, M_TOT * D_SZ / 4);
    // 2) transpose weights into K-major fp16
    transpose_half_kernel<<<dim3(H_SZ / 32, D_SZ / 32), dim3(32, 8)>>>(W1, W1T, D_SZ, H_SZ);
    transpose_half_kernel<<<dim3(D_SZ / 32, H_SZ / 32), dim3(32, 8)>>>(W2, W2T, H_SZ, D_SZ);
    // 3) GEMM1: T = GELU(X @ W1 + b1), fp16 output
    hmma_gemm<D_SZ, true><<<dim3(H_SZ / GBN, M_TOT / GBM), NTHR, SMEM_REQ>>>(
        Xh, W1T, b1, T, nullptr, H_SZ);
    // 4) GEMM2: out = T @ W2 + b2, fp32 output
    hmma_gemm<H_SZ, false><<<dim3(D_SZ / GBN, M_TOT / GBM), NTHR, SMEM_REQ>>>(
        T, W2T, b2, nullptr, out, D_SZ);
    // 5) out[:,0,:] = X[:,0,:]
    copy_first_token_kernel<<<(B_SZ * D_SZ + 255) / 256, 256>>>(X, out);
}